// round 1
// baseline (speedup 1.0000x reference)
#include <cuda_runtime.h>
#include <math.h>

// ---------------- problem constants (baked into reference) ----------------
#define R_NUM 5
#define N1T   30000
#define N2T   15000
#define IN_DIM 128
#define HC0   256
#define H0    4
#define C0    64
#define HC1   40
#define H1    1
#define C1    40
#define N0MAX 100000
#define E0MAX 300000
#define E1MAX 150000

// ---------------- scratch (static device arrays; no allocation) -----------
__device__ float g_x  [(size_t)N0MAX * IN_DIM];
__device__ float g_hj0[(size_t)N0MAX * HC0];
__device__ float g_hi0[(size_t)N1T   * HC0];
__device__ float g_exa0[(size_t)E0MAX * H0];
__device__ float g_den0[(size_t)N1T * R_NUM * H0];
__device__ float g_z0 [(size_t)R_NUM * N1T * HC0];
__device__ float g_q0 [(size_t)R_NUM * N1T * HC0];
__device__ float g_k0 [(size_t)R_NUM * N1T * HC0];
__device__ float g_v0 [(size_t)R_NUM * N1T * HC0];
__device__ float g_x1 [(size_t)N1T * HC0];
__device__ float g_hj1[(size_t)N1T * HC1];
__device__ float g_hi1[(size_t)N2T * HC1];
__device__ float g_exa1[(size_t)E1MAX * H1];
__device__ float g_den1[(size_t)N2T * R_NUM * H1];
__device__ float g_z1 [(size_t)R_NUM * N2T * HC1];
__device__ float g_q1 [(size_t)R_NUM * N2T * HC1];
__device__ float g_k1 [(size_t)R_NUM * N2T * HC1];
__device__ float g_v1 [(size_t)R_NUM * N2T * HC1];
__device__ float g_o1 [(size_t)N2T * HC1];

static inline int cdiv(int a, int b) { return (a + b - 1) / b; }

// ---------------- kernels -------------------------------------------------

// x[n,:] = emb[local_node_idx[n_id[n]], :]   (float4 per thread)
__global__ void gather_kernel(const float* __restrict__ emb,
                              const int* __restrict__ n_id,
                              const int* __restrict__ lni,
                              float* __restrict__ x, int N)
{
    const int D4 = IN_DIM / 4;
    int i = blockIdx.x * blockDim.x + threadIdx.x;
    int n = i / D4, d = i % D4;
    if (n >= N) return;
    int row = lni[n_id[n]];
    reinterpret_cast<float4*>(x)[(size_t)n * D4 + d] =
        reinterpret_cast<const float4*>(emb)[(size_t)row * D4 + d];
}

// C[M,N] = A[M,K] @ B[K,N]  (+ bias[N])  (+= if accumulate). Row-major all.
// 64x64 tile, 16x16 threads, 4x4 strided micro-tile, K-step 16.
__global__ void gemm_kernel(const float* __restrict__ A,
                            const float* __restrict__ B,
                            const float* __restrict__ bias,
                            float* __restrict__ C,
                            int M, int N, int K, int accumulate)
{
    __shared__ float As[16][65];
    __shared__ float Bs[16][64];
    int tx = threadIdx.x, ty = threadIdx.y;
    int tid = ty * 16 + tx;
    int m0 = blockIdx.y * 64, n0 = blockIdx.x * 64;
    float acc[4][4];
#pragma unroll
    for (int i = 0; i < 4; i++)
#pragma unroll
        for (int j = 0; j < 4; j++) acc[i][j] = 0.f;

    for (int k0 = 0; k0 < K; k0 += 16) {
#pragma unroll
        for (int i = 0; i < 4; i++) {
            int idx = tid + i * 256;            // 0..1023
            int m = idx >> 4, k = idx & 15;     // A tile 64x16
            float v = 0.f;
            if (m0 + m < M && k0 + k < K) v = A[(size_t)(m0 + m) * K + k0 + k];
            As[k][m] = v;
        }
#pragma unroll
        for (int i = 0; i < 4; i++) {
            int idx = tid + i * 256;
            int k = idx >> 6, n = idx & 63;     // B tile 16x64
            float v = 0.f;
            if (k0 + k < K && n0 + n < N) v = B[(size_t)(k0 + k) * N + n0 + n];
            Bs[k][n] = v;
        }
        __syncthreads();
#pragma unroll
        for (int kk = 0; kk < 16; kk++) {
            float a[4], b[4];
#pragma unroll
            for (int i = 0; i < 4; i++) a[i] = As[kk][ty + 16 * i];
#pragma unroll
            for (int j = 0; j < 4; j++) b[j] = Bs[kk][tx + 16 * j];
#pragma unroll
            for (int i = 0; i < 4; i++)
#pragma unroll
                for (int j = 0; j < 4; j++) acc[i][j] += a[i] * b[j];
        }
        __syncthreads();
    }
#pragma unroll
    for (int i = 0; i < 4; i++) {
        int m = m0 + ty + 16 * i;
        if (m >= M) continue;
#pragma unroll
        for (int j = 0; j < 4; j++) {
            int n = n0 + tx + 16 * j;
            if (n >= N) continue;
            float v = acc[i][j];
            if (bias) v += bias[n];
            size_t oi = (size_t)m * N + n;
            if (accumulate) v += C[oi];
            C[oi] = v;
        }
    }
}

// per-edge attention logits + exp, accumulate softmax denominator.
// one warp per edge. den layout: [(tgt*R + etype)*H + h]
__global__ void edge_alpha_kernel(const int* __restrict__ src,
                                  const int* __restrict__ tgt,
                                  const int* __restrict__ et,
                                  const float* __restrict__ hj,
                                  const float* __restrict__ hi,
                                  const float* __restrict__ attj,
                                  const float* __restrict__ atti,
                                  float* __restrict__ exa,
                                  float* __restrict__ den,
                                  int E, int H, int C)
{
    int w = (blockIdx.x * blockDim.x + threadIdx.x) >> 5;
    int lane = threadIdx.x & 31;
    if (w >= E) return;
    int t = et[w], s = src[w], g = tgt[w];
    const float* hjr = hj + (size_t)s * H * C;
    const float* hir = hi + (size_t)g * H * C;
    for (int h = 0; h < H; h++) {
        const float* ajw = attj + ((size_t)t * H + h) * C;
        const float* aiw = atti + ((size_t)t * H + h) * C;
        float aj = 0.f, ai = 0.f;
        for (int c = lane; c < C; c += 32) {
            aj += ajw[c] * hjr[h * C + c];
            ai += aiw[c] * hir[h * C + c];
        }
#pragma unroll
        for (int o = 16; o; o >>= 1) {
            aj += __shfl_xor_sync(0xffffffffu, aj, o);
            ai += __shfl_xor_sync(0xffffffffu, ai, o);
        }
        if (lane == 0) {
            float a = aj + ai;
            a = a >= 0.f ? a : 0.2f * a;           // leaky relu
            float ex = expf(a);                     // shift-invariant softmax: no max pass
            exa[(size_t)w * H + h] = ex;
            atomicAdd(&den[((size_t)g * R_NUM + t) * H + h], ex);
        }
    }
}

// scatter weighted messages into z[r][tgt][H*C]. one warp per edge.
__global__ void edge_scatter_kernel(const int* __restrict__ src,
                                    const int* __restrict__ tgt,
                                    const int* __restrict__ et,
                                    const float* __restrict__ hj,
                                    const float* __restrict__ exa,
                                    const float* __restrict__ den,
                                    float* __restrict__ z,
                                    int E, int Ntgt, int H, int C)
{
    int w = (blockIdx.x * blockDim.x + threadIdx.x) >> 5;
    int lane = threadIdx.x & 31;
    if (w >= E) return;
    int t = et[w], s = src[w], g = tgt[w];
    int HC = H * C;
    const float* hjr = hj + (size_t)s * HC;
    float* zr = z + ((size_t)t * Ntgt + g) * HC;
    for (int c = lane; c < HC; c += 32) {
        int h = c / C;
        float wgt = exa[(size_t)w * H + h] /
                    fmaxf(den[((size_t)g * R_NUM + t) * H + h], 1e-16f);
        atomicAdd(&zr[c], wgt * hjr[c]);
    }
}

// bilevel relation attention + Wrel combine + residual add (+optional relu).
// one warp per (node, head). q/k/v layout: [R][N][H*C].
__global__ void attn_kernel(const float* __restrict__ q,
                            const float* __restrict__ k,
                            const float* __restrict__ v,
                            const float* __restrict__ wrel,
                            float* __restrict__ out,
                            int N, int H, int C, int relu)
{
    int w = (blockIdx.x * blockDim.x + threadIdx.x) >> 5;
    int lane = threadIdx.x & 31;
    if (w >= N * H) return;
    int n = w / H, h = w % H;
    int HC = H * C;
    size_t base = (size_t)n * HC + h * C;
    size_t rs_stride = (size_t)N * HC;

    int c0 = lane, c1 = lane + 32;
    bool ok0 = c0 < C, ok1 = c1 < C;

    float qv[R_NUM][2], kv[R_NUM][2], vv[R_NUM][2];
#pragma unroll
    for (int r = 0; r < R_NUM; r++) {
        size_t o = (size_t)r * rs_stride + base;
        qv[r][0] = ok0 ? q[o + c0] : 0.f;  qv[r][1] = ok1 ? q[o + c1] : 0.f;
        kv[r][0] = ok0 ? k[o + c0] : 0.f;  kv[r][1] = ok1 ? k[o + c1] : 0.f;
        vv[r][0] = ok0 ? v[o + c0] : 0.f;  vv[r][1] = ok1 ? v[o + c1] : 0.f;
    }

    float psi[R_NUM][R_NUM];
#pragma unroll
    for (int r = 0; r < R_NUM; r++)
#pragma unroll
        for (int s = 0; s < R_NUM; s++) {
            float p = qv[r][0] * kv[s][0] + qv[r][1] * kv[s][1];
#pragma unroll
            for (int o = 16; o; o >>= 1) p += __shfl_xor_sync(0xffffffffu, p, o);
            psi[r][s] = p;
        }

    float wr[R_NUM];
#pragma unroll
    for (int r = 0; r < R_NUM; r++) wr[r] = wrel[r];

    float coeff[R_NUM] = {0.f, 0.f, 0.f, 0.f, 0.f};
#pragma unroll
    for (int r = 0; r < R_NUM; r++) {
        float rsum = 0.f;
#pragma unroll
        for (int s = 0; s < R_NUM; s++) rsum += psi[r][s];
        float pv[R_NUM], mx = -INFINITY;
#pragma unroll
        for (int s = 0; s < R_NUM; s++) {
            float x = psi[r][s];
            bool masked = (x == 0.f) && (rsum != 0.f);
            pv[s] = masked ? -INFINITY : x;
            mx = fmaxf(mx, pv[s]);
        }
        float pe[R_NUM], se = 0.f;
#pragma unroll
        for (int s = 0; s < R_NUM; s++) {
            float e = isinf(pv[s]) ? 0.f : expf(pv[s] - mx);
            pe[s] = e; se += e;
        }
        float inv = wr[r] / se;
#pragma unroll
        for (int s = 0; s < R_NUM; s++) coeff[s] += pe[s] * inv;
    }

    for (int j = 0; j < 2; j++) {
        int c = lane + 32 * j;
        if (c >= C) break;
        float acc = 0.f;
#pragma unroll
        for (int s = 0; s < R_NUM; s++) acc += coeff[s] * vv[s][j];
        size_t oi = base + c;
        float val = out[oi] + acc;
        out[oi] = relu ? fmaxf(val, 0.f) : val;
    }
}

// row-wise log_softmax, one warp per row (C <= 64)
__global__ void log_softmax_kernel(const float* __restrict__ in,
                                   float* __restrict__ out, int N, int C)
{
    int w = (blockIdx.x * blockDim.x + threadIdx.x) >> 5;
    int lane = threadIdx.x & 31;
    if (w >= N) return;
    int c0 = lane, c1 = lane + 32;
    float x0 = c0 < C ? in[(size_t)w * C + c0] : -INFINITY;
    float x1 = c1 < C ? in[(size_t)w * C + c1] : -INFINITY;
    float mx = fmaxf(x0, x1);
#pragma unroll
    for (int o = 16; o; o >>= 1) mx = fmaxf(mx, __shfl_xor_sync(0xffffffffu, mx, o));
    float se = (c0 < C ? expf(x0 - mx) : 0.f) + (c1 < C ? expf(x1 - mx) : 0.f);
#pragma unroll
    for (int o = 16; o; o >>= 1) se += __shfl_xor_sync(0xffffffffu, se, o);
    float lse = mx + logf(se);
    if (c0 < C) out[(size_t)w * C + c0] = x0 - lse;
    if (c1 < C) out[(size_t)w * C + c1] = x1 - lse;
}

// ---------------- host orchestration --------------------------------------

static void launch_gemm(const float* A, const float* B, const float* bias,
                        float* C, int M, int N, int K, int acc)
{
    dim3 grid(cdiv(N, 64), cdiv(M, 64));
    dim3 block(16, 16);
    gemm_kernel<<<grid, block>>>(A, B, bias, C, M, N, K, acc);
}

extern "C" void kernel_launch(void* const* d_in, const int* in_sizes, int n_in,
                              void* d_out, int out_size)
{
    const int*   n_id  = (const int*)d_in[0];
    const int*   lni   = (const int*)d_in[1];
    const int*   ei0   = (const int*)d_in[3];
    const int*   et0   = (const int*)d_in[4];
    const int*   ei1   = (const int*)d_in[5];
    const int*   et1   = (const int*)d_in[6];
    const float* emb   = (const float*)d_in[7];
    const float* Wj0   = (const float*)d_in[8];
    const float* Wi0   = (const float*)d_in[9];
    const float* attj0 = (const float*)d_in[10];
    const float* atti0 = (const float*)d_in[11];
    const float* Wq0   = (const float*)d_in[12];
    const float* Wk0   = (const float*)d_in[13];
    const float* Wv0   = (const float*)d_in[14];
    const float* sw0   = (const float*)d_in[15];
    const float* sb0   = (const float*)d_in[16];
    const float* Wrel0 = (const float*)d_in[17];
    const float* Wj1   = (const float*)d_in[18];
    const float* Wi1   = (const float*)d_in[19];
    const float* attj1 = (const float*)d_in[20];
    const float* atti1 = (const float*)d_in[21];
    const float* Wq1   = (const float*)d_in[22];
    const float* Wk1   = (const float*)d_in[23];
    const float* Wv1   = (const float*)d_in[24];
    const float* sw1   = (const float*)d_in[25];
    const float* sb1   = (const float*)d_in[26];
    const float* Wrel1 = (const float*)d_in[27];

    int N0 = in_sizes[0];
    int E0 = in_sizes[4];
    int E1 = in_sizes[6];

    float *x, *hj0, *hi0, *exa0, *den0, *z0, *q0, *k0, *v0, *x1;
    float *hj1, *hi1, *exa1, *den1, *z1, *q1, *k1, *v1, *o1;
    cudaGetSymbolAddress((void**)&x,    g_x);
    cudaGetSymbolAddress((void**)&hj0,  g_hj0);
    cudaGetSymbolAddress((void**)&hi0,  g_hi0);
    cudaGetSymbolAddress((void**)&exa0, g_exa0);
    cudaGetSymbolAddress((void**)&den0, g_den0);
    cudaGetSymbolAddress((void**)&z0,   g_z0);
    cudaGetSymbolAddress((void**)&q0,   g_q0);
    cudaGetSymbolAddress((void**)&k0,   g_k0);
    cudaGetSymbolAddress((void**)&v0,   g_v0);
    cudaGetSymbolAddress((void**)&x1,   g_x1);
    cudaGetSymbolAddress((void**)&hj1,  g_hj1);
    cudaGetSymbolAddress((void**)&hi1,  g_hi1);
    cudaGetSymbolAddress((void**)&exa1, g_exa1);
    cudaGetSymbolAddress((void**)&den1, g_den1);
    cudaGetSymbolAddress((void**)&z1,   g_z1);
    cudaGetSymbolAddress((void**)&q1,   g_q1);
    cudaGetSymbolAddress((void**)&k1,   g_k1);
    cudaGetSymbolAddress((void**)&v1,   g_v1);
    cudaGetSymbolAddress((void**)&o1,   g_o1);

    // ---- input gather ----
    {
        int total = N0 * (IN_DIM / 4);
        gather_kernel<<<cdiv(total, 256), 256>>>(emb, n_id, lni, x, N0);
    }

    // ---- layer 0 ----
    launch_gemm(x, Wj0, nullptr, hj0, N0,  HC0, IN_DIM, 0);
    launch_gemm(x, Wi0, nullptr, hi0, N1T, HC0, IN_DIM, 0);

    cudaMemsetAsync(den0, 0, (size_t)N1T * R_NUM * H0 * sizeof(float), 0);
    cudaMemsetAsync(z0,   0, (size_t)R_NUM * N1T * HC0 * sizeof(float), 0);

    edge_alpha_kernel<<<cdiv(E0 * 32, 256), 256>>>(
        ei0, ei0 + E0, et0, hj0, hi0, attj0, atti0, exa0, den0, E0, H0, C0);
    edge_scatter_kernel<<<cdiv(E0 * 32, 256), 256>>>(
        ei0, ei0 + E0, et0, hj0, exa0, den0, z0, E0, N1T, H0, C0);

    for (int r = 0; r < R_NUM; r++) {
        size_t zo = (size_t)r * N1T * HC0;
        size_t wo = (size_t)r * HC0 * HC0;
        launch_gemm(z0 + zo, Wq0 + wo, nullptr, q0 + zo, N1T, HC0, HC0, 0);
        launch_gemm(z0 + zo, Wk0 + wo, nullptr, k0 + zo, N1T, HC0, HC0, 0);
        launch_gemm(z0 + zo, Wv0 + wo, nullptr, v0 + zo, N1T, HC0, HC0, 0);
    }

    launch_gemm(x, sw0, sb0, x1, N1T, HC0, IN_DIM, 0);   // self term + bias
    attn_kernel<<<cdiv(N1T * H0 * 32, 256), 256>>>(
        q0, k0, v0, Wrel0, x1, N1T, H0, C0, /*relu=*/1);

    // ---- layer 1 ----
    launch_gemm(x1, Wj1, nullptr, hj1, N1T, HC1, HC0, 0);
    launch_gemm(x1, Wi1, nullptr, hi1, N2T, HC1, HC0, 0);

    cudaMemsetAsync(den1, 0, (size_t)N2T * R_NUM * H1 * sizeof(float), 0);
    cudaMemsetAsync(z1,   0, (size_t)R_NUM * N2T * HC1 * sizeof(float), 0);

    edge_alpha_kernel<<<cdiv(E1 * 32, 256), 256>>>(
        ei1, ei1 + E1, et1, hj1, hi1, attj1, atti1, exa1, den1, E1, H1, C1);
    edge_scatter_kernel<<<cdiv(E1 * 32, 256), 256>>>(
        ei1, ei1 + E1, et1, hj1, exa1, den1, z1, E1, N2T, H1, C1);

    for (int r = 0; r < R_NUM; r++) {
        size_t zo = (size_t)r * N2T * HC1;
        size_t wo = (size_t)r * HC1 * HC1;
        launch_gemm(z1 + zo, Wq1 + wo, nullptr, q1 + zo, N2T, HC1, HC1, 0);
        launch_gemm(z1 + zo, Wk1 + wo, nullptr, k1 + zo, N2T, HC1, HC1, 0);
        launch_gemm(z1 + zo, Wv1 + wo, nullptr, v1 + zo, N2T, HC1, HC1, 0);
    }

    launch_gemm(x1, sw1, sb1, o1, N2T, HC1, HC0, 0);     // self term + bias
    attn_kernel<<<cdiv(N2T * H1 * 32, 256), 256>>>(
        q1, k1, v1, Wrel1, o1, N2T, H1, C1, /*relu=*/0);

    // ---- output ----
    log_softmax_kernel<<<cdiv(N2T * 32, 256), 256>>>(o1, (float*)d_out, N2T, C1);
}

// round 3
// speedup vs baseline: 4.4976x; 4.4976x over previous
#include <cuda_runtime.h>
#include <cuda_bf16.h>
#include <math.h>

// ---------------- problem constants ----------------
#define R_NUM 5
#define N1T   30000
#define N2T   15000
#define IN_DIM 128
#define HC0   256
#define H0    4
#define C0    64
#define HC1   40
#define H1    1
#define C1    40
#define E0MAX 300000
#define E1MAX 150000

// ---------------- scratch ----------------
__device__ float g_x   [(size_t)N1T * IN_DIM];
__device__ __nv_bfloat16 g_xbf[(size_t)N1T * IN_DIM];
__device__ float g_hj0 [(size_t)N1T * HC0];
__device__ float g_hi0 [(size_t)N2T * HC0];
__device__ float g_exa0[(size_t)E0MAX * H0];
__device__ float g_den0[(size_t)N2T * R_NUM * H0];
__device__ float g_z0  [(size_t)R_NUM * N2T * HC0];
__device__ __nv_bfloat16 g_z0bf[(size_t)R_NUM * N2T * HC0];
__device__ float g_q0  [(size_t)R_NUM * N2T * HC0];
__device__ float g_k0  [(size_t)R_NUM * N2T * HC0];
__device__ float g_v0  [(size_t)R_NUM * N2T * HC0];
__device__ float g_x1  [(size_t)N2T * HC0];
__device__ __nv_bfloat16 g_x1bf[(size_t)N2T * HC0];
__device__ float g_hj1 [(size_t)N2T * HC1];
__device__ float g_hi1 [(size_t)N2T * HC1];
__device__ float g_exa1[(size_t)E1MAX * H1];
__device__ float g_den1[(size_t)N2T * R_NUM * H1];
__device__ float g_z1  [(size_t)R_NUM * N2T * HC1];
__device__ float g_q1  [(size_t)R_NUM * N2T * HC1];
__device__ float g_k1  [(size_t)R_NUM * N2T * HC1];
__device__ float g_v1  [(size_t)R_NUM * N2T * HC1];
__device__ float g_o1  [(size_t)N2T * HC1];
// transposed bf16 weights [N][K]
__device__ __nv_bfloat16 g_wj0t[(size_t)HC0 * IN_DIM];
__device__ __nv_bfloat16 g_wi0t[(size_t)HC0 * IN_DIM];
__device__ __nv_bfloat16 g_sw0t[(size_t)HC0 * IN_DIM];
__device__ __nv_bfloat16 g_wq0t[(size_t)R_NUM * HC0 * HC0];
__device__ __nv_bfloat16 g_wk0t[(size_t)R_NUM * HC0 * HC0];
__device__ __nv_bfloat16 g_wv0t[(size_t)R_NUM * HC0 * HC0];
__device__ __nv_bfloat16 g_wj1t[(size_t)HC1 * HC0];
__device__ __nv_bfloat16 g_wi1t[(size_t)HC1 * HC0];
__device__ __nv_bfloat16 g_sw1t[(size_t)HC1 * HC0];

static inline int cdiv(int a, int b) { return (a + b - 1) / b; }

// ---------------- utility kernels ----------------

__global__ void gather_kernel(const float* __restrict__ emb,
                              const int* __restrict__ n_id,
                              const int* __restrict__ lni,
                              float* __restrict__ x, int N)
{
    const int D4 = IN_DIM / 4;
    int i = blockIdx.x * blockDim.x + threadIdx.x;
    int n = i / D4, d = i % D4;
    if (n >= N) return;
    int row = lni[n_id[n]];
    reinterpret_cast<float4*>(x)[(size_t)n * D4 + d] =
        reinterpret_cast<const float4*>(emb)[(size_t)row * D4 + d];
}

__global__ void f2bf_kernel(const float* __restrict__ in,
                            __nv_bfloat16* __restrict__ out, size_t n)
{
    size_t i = (size_t)blockIdx.x * blockDim.x + threadIdx.x;
    if (i < n) out[i] = __float2bfloat16(in[i]);
}

// in [batch][Kd][Nd] f32 -> out [batch][Nd][Kd] bf16
__global__ void tconv_kernel(const float* __restrict__ in,
                             __nv_bfloat16* __restrict__ out,
                             int Kd, int Nd, int batch)
{
    int i = blockIdx.x * blockDim.x + threadIdx.x;
    int per = Kd * Nd;
    if (i >= per * batch) return;
    int b = i / per, rem = i - b * per;
    int k = rem / Nd, n = rem - k * Nd;
    out[(size_t)b * per + (size_t)n * Kd + k] = __float2bfloat16(in[i]);
}

// ---------------- bf16 tensor-core GEMM ----------------
// C[M,N] (f32) = A[M,K](bf16,row-major) @ Bt[N,K](bf16) (+bias)
// block 128x128x32, 256 threads = 8 warps (4 M x 2 N), warp tile 32x64.

__device__ __forceinline__ void mma16816(float* d, const unsigned* a,
                                         const unsigned* b, const float* c)
{
    asm volatile(
        "mma.sync.aligned.m16n8k16.row.col.f32.bf16.bf16.f32 "
        "{%0,%1,%2,%3}, {%4,%5,%6,%7}, {%8,%9}, {%10,%11,%12,%13};\n"
        : "=f"(d[0]), "=f"(d[1]), "=f"(d[2]), "=f"(d[3])
        : "r"(a[0]), "r"(a[1]), "r"(a[2]), "r"(a[3]),
          "r"(b[0]), "r"(b[1]),
          "f"(c[0]), "f"(c[1]), "f"(c[2]), "f"(c[3]));
}

#define TBM 128
#define TBN 128
#define TBK 32
#define TLD 40   // smem row stride (bf16 elems): 32 + 8 pad -> conflict-free

__device__ __forceinline__ void gemm_tc_body(const __nv_bfloat16* __restrict__ A,
                                             const __nv_bfloat16* __restrict__ Bt,
                                             const float* __restrict__ bias,
                                             float* __restrict__ C,
                                             int M, int N, int K)
{
    __shared__ __nv_bfloat16 As[TBM * TLD];
    __shared__ __nv_bfloat16 Bs[TBN * TLD];
    int tid = threadIdx.x;
    int wid = tid >> 5, lane = tid & 31;
    int wm = wid >> 1, wn = wid & 1;
    int m0 = blockIdx.y * TBM, n0 = blockIdx.x * TBN;
    int g = lane >> 2, cq = lane & 3;

    float acc[2][8][4];
#pragma unroll
    for (int i = 0; i < 2; i++)
#pragma unroll
        for (int j = 0; j < 8; j++)
#pragma unroll
            for (int q = 0; q < 4; q++) acc[i][j][q] = 0.f;

    const float4 zero4 = make_float4(0.f, 0.f, 0.f, 0.f);

    for (int kt = 0; kt < K; kt += TBK) {
#pragma unroll
        for (int it = 0; it < 2; it++) {
            int idx = tid + it * 256;            // 0..511
            int r = idx >> 2, kg = (idx & 3) * 8;
            int gk = kt + kg;
            float4 va = zero4, vb = zero4;
            if (m0 + r < M)
                va = *reinterpret_cast<const float4*>(A + (size_t)(m0 + r) * K + gk);
            if (n0 + r < N)
                vb = *reinterpret_cast<const float4*>(Bt + (size_t)(n0 + r) * K + gk);
            *reinterpret_cast<float4*>(&As[r * TLD + kg]) = va;
            *reinterpret_cast<float4*>(&Bs[r * TLD + kg]) = vb;
        }
        __syncthreads();
#pragma unroll
        for (int ks = 0; ks < 2; ks++) {
            int kb = ks * 16;
            unsigned a[2][4], b[8][2];
#pragma unroll
            for (int mf = 0; mf < 2; mf++) {
                const __nv_bfloat16* p = &As[(wm * 32 + mf * 16 + g) * TLD + kb + cq * 2];
                a[mf][0] = *reinterpret_cast<const unsigned*>(p);
                a[mf][1] = *reinterpret_cast<const unsigned*>(p + 8 * TLD);
                a[mf][2] = *reinterpret_cast<const unsigned*>(p + 8);
                a[mf][3] = *reinterpret_cast<const unsigned*>(p + 8 * TLD + 8);
            }
#pragma unroll
            for (int nf = 0; nf < 8; nf++) {
                const __nv_bfloat16* p = &Bs[(wn * 64 + nf * 8 + g) * TLD + kb + cq * 2];
                b[nf][0] = *reinterpret_cast<const unsigned*>(p);
                b[nf][1] = *reinterpret_cast<const unsigned*>(p + 8);
            }
#pragma unroll
            for (int mf = 0; mf < 2; mf++)
#pragma unroll
                for (int nf = 0; nf < 8; nf++)
                    mma16816(acc[mf][nf], a[mf], b[nf], acc[mf][nf]);
        }
        __syncthreads();
    }

#pragma unroll
    for (int mf = 0; mf < 2; mf++) {
#pragma unroll
        for (int nf = 0; nf < 8; nf++) {
            int col = n0 + wn * 64 + nf * 8 + cq * 2;
            int row = m0 + wm * 32 + mf * 16 + g;
            if (col >= N) continue;                // N is a multiple of 8
            float b0 = 0.f, b1 = 0.f;
            if (bias) { b0 = bias[col]; b1 = bias[col + 1]; }
            if (row < M) {
                float2 v = make_float2(acc[mf][nf][0] + b0, acc[mf][nf][1] + b1);
                *reinterpret_cast<float2*>(C + (size_t)row * N + col) = v;
            }
            if (row + 8 < M) {
                float2 v = make_float2(acc[mf][nf][2] + b0, acc[mf][nf][3] + b1);
                *reinterpret_cast<float2*>(C + (size_t)(row + 8) * N + col) = v;
            }
        }
    }
}

__global__ void gemm_tc_kernel(const __nv_bfloat16* __restrict__ A,
                               const __nv_bfloat16* __restrict__ Bt,
                               const float* __restrict__ bias,
                               float* __restrict__ C, int M, int N, int K)
{
    gemm_tc_body(A, Bt, bias, C, M, N, K);
}

// batched q/k/v over gridDim.z = 3*R: z = r*3 + which
__global__ void gemm_qkv_tc_kernel(const __nv_bfloat16* __restrict__ A, size_t sA,
                                   const __nv_bfloat16* __restrict__ Bq,
                                   const __nv_bfloat16* __restrict__ Bk,
                                   const __nv_bfloat16* __restrict__ Bv, size_t sB,
                                   float* __restrict__ Cq, float* __restrict__ Ck,
                                   float* __restrict__ Cv, size_t sC,
                                   int M, int N, int K)
{
    int z = blockIdx.z;
    int r = z / 3, which = z - r * 3;
    const __nv_bfloat16* B = (which == 0) ? Bq : (which == 1) ? Bk : Bv;
    float* C = (which == 0) ? Cq : (which == 1) ? Ck : Cv;
    gemm_tc_body(A + (size_t)r * sA, B + (size_t)r * sB, nullptr,
                 C + (size_t)r * sC, M, N, K);
}

// ---------------- fp32 fallback GEMM (small layer-1 qkv) ----------------
__global__ void gemm_kernel(const float* __restrict__ A,
                            const float* __restrict__ B,
                            float* __restrict__ C,
                            int M, int N, int K)
{
    __shared__ float As[16][65];
    __shared__ float Bs[16][64];
    int tx = threadIdx.x, ty = threadIdx.y;
    int tid = ty * 16 + tx;
    int m0 = blockIdx.y * 64, n0 = blockIdx.x * 64;
    float acc[4][4];
#pragma unroll
    for (int i = 0; i < 4; i++)
#pragma unroll
        for (int j = 0; j < 4; j++) acc[i][j] = 0.f;

    for (int k0 = 0; k0 < K; k0 += 16) {
#pragma unroll
        for (int i = 0; i < 4; i++) {
            int idx = tid + i * 256;
            int m = idx >> 4, k = idx & 15;
            float v = 0.f;
            if (m0 + m < M && k0 + k < K) v = A[(size_t)(m0 + m) * K + k0 + k];
            As[k][m] = v;
        }
#pragma unroll
        for (int i = 0; i < 4; i++) {
            int idx = tid + i * 256;
            int k = idx >> 6, n = idx & 63;
            float v = 0.f;
            if (k0 + k < K && n0 + n < N) v = B[(size_t)(k0 + k) * N + n0 + n];
            Bs[k][n] = v;
        }
        __syncthreads();
#pragma unroll
        for (int kk = 0; kk < 16; kk++) {
            float a[4], b[4];
#pragma unroll
            for (int i = 0; i < 4; i++) a[i] = As[kk][ty + 16 * i];
#pragma unroll
            for (int j = 0; j < 4; j++) b[j] = Bs[kk][tx + 16 * j];
#pragma unroll
            for (int i = 0; i < 4; i++)
#pragma unroll
                for (int j = 0; j < 4; j++) acc[i][j] += a[i] * b[j];
        }
        __syncthreads();
    }
#pragma unroll
    for (int i = 0; i < 4; i++) {
        int m = m0 + ty + 16 * i;
        if (m >= M) continue;
#pragma unroll
        for (int j = 0; j < 4; j++) {
            int n = n0 + tx + 16 * j;
            if (n >= N) continue;
            C[(size_t)m * N + n] = acc[i][j];
        }
    }
}

// ---------------- edge kernels ----------------

// fast path: H=4, C=64, HC=256; skip edges with tgt >= limit
__global__ void edge_alpha0_kernel(const int* __restrict__ src,
                                   const int* __restrict__ tgt,
                                   const int* __restrict__ et,
                                   const float* __restrict__ hj,
                                   const float* __restrict__ hi,
                                   const float* __restrict__ attj,
                                   const float* __restrict__ atti,
                                   float* __restrict__ exa,
                                   float* __restrict__ den,
                                   int E, int limit)
{
    int w = (blockIdx.x * blockDim.x + threadIdx.x) >> 5;
    int lane = threadIdx.x & 31;
    if (w >= E) return;
    int gnode = tgt[w];
    if (gnode >= limit) return;
    int t = et[w], s = src[w];
    int h = lane >> 3, j = lane & 7;
    const float* hjh = hj + (size_t)s * 256 + h * 64;
    const float* hih = hi + (size_t)gnode * 256 + h * 64;
    const float* ajh = attj + ((size_t)t * 4 + h) * 64;
    const float* aih = atti + ((size_t)t * 4 + h) * 64;
    float acc = 0.f;
#pragma unroll
    for (int u = 0; u < 8; u++) {
        int c = j + 8 * u;
        acc += ajh[c] * hjh[c] + aih[c] * hih[c];
    }
#pragma unroll
    for (int o = 4; o; o >>= 1) acc += __shfl_xor_sync(0xffffffffu, acc, o);
    if (j == 0) {
        float a = acc >= 0.f ? acc : 0.2f * acc;
        float ex = expf(a);
        exa[(size_t)w * 4 + h] = ex;
        atomicAdd(&den[((size_t)gnode * R_NUM + t) * 4 + h], ex);
    }
}

// generic (layer 1: H=1, C=40)
__global__ void edge_alpha_kernel(const int* __restrict__ src,
                                  const int* __restrict__ tgt,
                                  const int* __restrict__ et,
                                  const float* __restrict__ hj,
                                  const float* __restrict__ hi,
                                  const float* __restrict__ attj,
                                  const float* __restrict__ atti,
                                  float* __restrict__ exa,
                                  float* __restrict__ den,
                                  int E, int H, int C)
{
    int w = (blockIdx.x * blockDim.x + threadIdx.x) >> 5;
    int lane = threadIdx.x & 31;
    if (w >= E) return;
    int t = et[w], s = src[w], gnode = tgt[w];
    const float* hjr = hj + (size_t)s * H * C;
    const float* hir = hi + (size_t)gnode * H * C;
    for (int h = 0; h < H; h++) {
        const float* ajw = attj + ((size_t)t * H + h) * C;
        const float* aiw = atti + ((size_t)t * H + h) * C;
        float acc = 0.f;
        for (int c = lane; c < C; c += 32)
            acc += ajw[c] * hjr[h * C + c] + aiw[c] * hir[h * C + c];
#pragma unroll
        for (int o = 16; o; o >>= 1) acc += __shfl_xor_sync(0xffffffffu, acc, o);
        if (lane == 0) {
            float a = acc >= 0.f ? acc : 0.2f * acc;
            float ex = expf(a);
            exa[(size_t)w * H + h] = ex;
            atomicAdd(&den[((size_t)gnode * R_NUM + t) * H + h], ex);
        }
    }
}

__global__ void edge_scatter_kernel(const int* __restrict__ src,
                                    const int* __restrict__ tgt,
                                    const int* __restrict__ et,
                                    const float* __restrict__ hj,
                                    const float* __restrict__ exa,
                                    const float* __restrict__ den,
                                    float* __restrict__ z,
                                    int E, int Ntgt, int H, int C, int limit)
{
    int w = (blockIdx.x * blockDim.x + threadIdx.x) >> 5;
    int lane = threadIdx.x & 31;
    if (w >= E) return;
    int gnode = tgt[w];
    if (gnode >= limit) return;
    int t = et[w], s = src[w];
    int HC = H * C;
    const float* hjr = hj + (size_t)s * HC;
    float* zr = z + ((size_t)t * Ntgt + gnode) * HC;
    for (int c = lane; c < HC; c += 32) {
        int h = c / C;
        float wgt = exa[(size_t)w * H + h] /
                    fmaxf(den[((size_t)gnode * R_NUM + t) * H + h], 1e-16f);
        atomicAdd(&zr[c], wgt * hjr[c]);
    }
}

// ---------------- bilevel relation attention ----------------
__global__ void attn_kernel(const float* __restrict__ q,
                            const float* __restrict__ k,
                            const float* __restrict__ v,
                            const float* __restrict__ wrel,
                            float* __restrict__ out,
                            int N, int H, int C, int relu)
{
    int w = (blockIdx.x * blockDim.x + threadIdx.x) >> 5;
    int lane = threadIdx.x & 31;
    if (w >= N * H) return;
    int n = w / H, h = w - n * H;
    int HC = H * C;
    size_t base = (size_t)n * HC + h * C;
    size_t rs_stride = (size_t)N * HC;

    int c0 = lane, c1 = lane + 32;
    bool ok0 = c0 < C, ok1 = c1 < C;

    float qv[R_NUM][2], kv[R_NUM][2], vv[R_NUM][2];
#pragma unroll
    for (int r = 0; r < R_NUM; r++) {
        size_t o = (size_t)r * rs_stride + base;
        qv[r][0] = ok0 ? q[o + c0] : 0.f;  qv[r][1] = ok1 ? q[o + c1] : 0.f;
        kv[r][0] = ok0 ? k[o + c0] : 0.f;  kv[r][1] = ok1 ? k[o + c1] : 0.f;
        vv[r][0] = ok0 ? v[o + c0] : 0.f;  vv[r][1] = ok1 ? v[o + c1] : 0.f;
    }

    float psi[R_NUM][R_NUM];
#pragma unroll
    for (int r = 0; r < R_NUM; r++)
#pragma unroll
        for (int s = 0; s < R_NUM; s++) {
            float p = qv[r][0] * kv[s][0] + qv[r][1] * kv[s][1];
#pragma unroll
            for (int o = 16; o; o >>= 1) p += __shfl_xor_sync(0xffffffffu, p, o);
            psi[r][s] = p;
        }

    float coeff[R_NUM] = {0.f, 0.f, 0.f, 0.f, 0.f};
#pragma unroll
    for (int r = 0; r < R_NUM; r++) {
        float rsum = 0.f;
#pragma unroll
        for (int s = 0; s < R_NUM; s++) rsum += psi[r][s];
        float pv[R_NUM], mx = -INFINITY;
#pragma unroll
        for (int s = 0; s < R_NUM; s++) {
            float xx = psi[r][s];
            bool masked = (xx == 0.f) && (rsum != 0.f);
            pv[s] = masked ? -INFINITY : xx;
            mx = fmaxf(mx, pv[s]);
        }
        float pe[R_NUM], se = 0.f;
#pragma unroll
        for (int s = 0; s < R_NUM; s++) {
            float e = isinf(pv[s]) ? 0.f : expf(pv[s] - mx);
            pe[s] = e; se += e;
        }
        float inv = wrel[r] / se;
#pragma unroll
        for (int s = 0; s < R_NUM; s++) coeff[s] += pe[s] * inv;
    }

    for (int jj = 0; jj < 2; jj++) {
        int c = lane + 32 * jj;
        if (c >= C) break;
        float acc = 0.f;
#pragma unroll
        for (int s = 0; s < R_NUM; s++) acc += coeff[s] * vv[s][jj];
        size_t oi = base + c;
        float val = out[oi] + acc;
        out[oi] = relu ? fmaxf(val, 0.f) : val;
    }
}

__global__ void log_softmax_kernel(const float* __restrict__ in,
                                   float* __restrict__ out, int N, int C)
{
    int w = (blockIdx.x * blockDim.x + threadIdx.x) >> 5;
    int lane = threadIdx.x & 31;
    if (w >= N) return;
    int c0 = lane, c1 = lane + 32;
    float x0 = c0 < C ? in[(size_t)w * C + c0] : -INFINITY;
    float x1 = c1 < C ? in[(size_t)w * C + c1] : -INFINITY;
    float mx = fmaxf(x0, x1);
#pragma unroll
    for (int o = 16; o; o >>= 1) mx = fmaxf(mx, __shfl_xor_sync(0xffffffffu, mx, o));
    float se = (c0 < C ? expf(x0 - mx) : 0.f) + (c1 < C ? expf(x1 - mx) : 0.f);
#pragma unroll
    for (int o = 16; o; o >>= 1) se += __shfl_xor_sync(0xffffffffu, se, o);
    float lse = mx + logf(se);
    if (c0 < C) out[(size_t)w * C + c0] = x0 - lse;
    if (c1 < C) out[(size_t)w * C + c1] = x1 - lse;
}

// ---------------- host ----------------

static void tc_gemm(const __nv_bfloat16* A, const __nv_bfloat16* Bt,
                    const float* bias, float* C, int M, int N, int K)
{
    dim3 grid(cdiv(N, TBN), cdiv(M, TBM));
    gemm_tc_kernel<<<grid, 256>>>(A, Bt, bias, C, M, N, K);
}

extern "C" void kernel_launch(void* const* d_in, const int* in_sizes, int n_in,
                              void* d_out, int out_size)
{
    const int*   n_id  = (const int*)d_in[0];
    const int*   lni   = (const int*)d_in[1];
    const int*   ei0   = (const int*)d_in[3];
    const int*   et0   = (const int*)d_in[4];
    const int*   ei1   = (const int*)d_in[5];
    const int*   et1   = (const int*)d_in[6];
    const float* emb   = (const float*)d_in[7];
    const float* Wj0   = (const float*)d_in[8];
    const float* Wi0   = (const float*)d_in[9];
    const float* attj0 = (const float*)d_in[10];
    const float* atti0 = (const float*)d_in[11];
    const float* Wq0   = (const float*)d_in[12];
    const float* Wk0   = (const float*)d_in[13];
    const float* Wv0   = (const float*)d_in[14];
    const float* sw0   = (const float*)d_in[15];
    const float* sb0   = (const float*)d_in[16];
    const float* Wrel0 = (const float*)d_in[17];
    const float* Wj1   = (const float*)d_in[18];
    const float* Wi1   = (const float*)d_in[19];
    const float* attj1 = (const float*)d_in[20];
    const float* atti1 = (const float*)d_in[21];
    const float* Wq1   = (const float*)d_in[22];
    const float* Wk1   = (const float*)d_in[23];
    const float* Wv1   = (const float*)d_in[24];
    const float* sw1   = (const float*)d_in[25];
    const float* sb1   = (const float*)d_in[26];
    const float* Wrel1 = (const float*)d_in[27];

    int E0 = in_sizes[4];
    int E1 = in_sizes[6];

    float *x, *hj0, *hi0, *exa0, *den0, *z0, *q0, *k0, *v0, *x1;
    float *hj1, *hi1, *exa1, *den1, *z1, *q1, *k1, *v1, *o1;
    __nv_bfloat16 *xbf, *z0bf, *x1bf;
    __nv_bfloat16 *wj0t, *wi0t, *sw0t, *wq0t, *wk0t, *wv0t, *wj1t, *wi1t, *sw1t;
    cudaGetSymbolAddress((void**)&x,    g_x);
    cudaGetSymbolAddress((void**)&xbf,  g_xbf);
    cudaGetSymbolAddress((void**)&hj0,  g_hj0);
    cudaGetSymbolAddress((void**)&hi0,  g_hi0);
    cudaGetSymbolAddress((void**)&exa0, g_exa0);
    cudaGetSymbolAddress((void**)&den0, g_den0);
    cudaGetSymbolAddress((void**)&z0,   g_z0);
    cudaGetSymbolAddress((void**)&z0bf, g_z0bf);
    cudaGetSymbolAddress((void**)&q0,   g_q0);
    cudaGetSymbolAddress((void**)&k0,   g_k0);
    cudaGetSymbolAddress((void**)&v0,   g_v0);
    cudaGetSymbolAddress((void**)&x1,   g_x1);
    cudaGetSymbolAddress((void**)&x1bf, g_x1bf);
    cudaGetSymbolAddress((void**)&hj1,  g_hj1);
    cudaGetSymbolAddress((void**)&hi1,  g_hi1);
    cudaGetSymbolAddress((void**)&exa1, g_exa1);
    cudaGetSymbolAddress((void**)&den1, g_den1);
    cudaGetSymbolAddress((void**)&z1,   g_z1);
    cudaGetSymbolAddress((void**)&q1,   g_q1);
    cudaGetSymbolAddress((void**)&k1,   g_k1);
    cudaGetSymbolAddress((void**)&v1,   g_v1);
    cudaGetSymbolAddress((void**)&o1,   g_o1);
    cudaGetSymbolAddress((void**)&wj0t, g_wj0t);
    cudaGetSymbolAddress((void**)&wi0t, g_wi0t);
    cudaGetSymbolAddress((void**)&sw0t, g_sw0t);
    cudaGetSymbolAddress((void**)&wq0t, g_wq0t);
    cudaGetSymbolAddress((void**)&wk0t, g_wk0t);
    cudaGetSymbolAddress((void**)&wv0t, g_wv0t);
    cudaGetSymbolAddress((void**)&wj1t, g_wj1t);
    cudaGetSymbolAddress((void**)&wi1t, g_wi1t);
    cudaGetSymbolAddress((void**)&sw1t, g_sw1t);

    // ---- gather only the 30000 rows layer-0 can reference ----
    {
        int total = N1T * (IN_DIM / 4);
        gather_kernel<<<cdiv(total, 256), 256>>>(emb, n_id, lni, x, N1T);
    }
    f2bf_kernel<<<cdiv(N1T * IN_DIM, 256), 256>>>(x, xbf, (size_t)N1T * IN_DIM);

    // ---- weight transpose+convert ----
    tconv_kernel<<<cdiv(IN_DIM * HC0, 256), 256>>>(Wj0, wj0t, IN_DIM, HC0, 1);
    tconv_kernel<<<cdiv(IN_DIM * HC0, 256), 256>>>(Wi0, wi0t, IN_DIM, HC0, 1);
    tconv_kernel<<<cdiv(IN_DIM * HC0, 256), 256>>>(sw0, sw0t, IN_DIM, HC0, 1);
    tconv_kernel<<<cdiv(R_NUM * HC0 * HC0, 256), 256>>>(Wq0, wq0t, HC0, HC0, R_NUM);
    tconv_kernel<<<cdiv(R_NUM * HC0 * HC0, 256), 256>>>(Wk0, wk0t, HC0, HC0, R_NUM);
    tconv_kernel<<<cdiv(R_NUM * HC0 * HC0, 256), 256>>>(Wv0, wv0t, HC0, HC0, R_NUM);
    tconv_kernel<<<cdiv(HC0 * HC1, 256), 256>>>(Wj1, wj1t, HC0, HC1, 1);
    tconv_kernel<<<cdiv(HC0 * HC1, 256), 256>>>(Wi1, wi1t, HC0, HC1, 1);
    tconv_kernel<<<cdiv(HC0 * HC1, 256), 256>>>(sw1, sw1t, HC0, HC1, 1);

    // ---- layer 0 ----
    tc_gemm(xbf, wj0t, nullptr, hj0, N1T, HC0, IN_DIM);   // 30000 rows (src range)
    tc_gemm(xbf, wi0t, nullptr, hi0, N2T, HC0, IN_DIM);   // only live targets
    tc_gemm(xbf, sw0t, sb0,     x1,  N2T, HC0, IN_DIM);   // self term

    cudaMemsetAsync(den0, 0, (size_t)N2T * R_NUM * H0 * sizeof(float), 0);
    cudaMemsetAsync(z0,   0, (size_t)R_NUM * N2T * HC0 * sizeof(float), 0);

    edge_alpha0_kernel<<<cdiv(E0 * 32, 256), 256>>>(
        ei0, ei0 + E0, et0, hj0, hi0, attj0, atti0, exa0, den0, E0, N2T);
    edge_scatter_kernel<<<cdiv(E0 * 32, 256), 256>>>(
        ei0, ei0 + E0, et0, hj0, exa0, den0, z0, E0, N2T, H0, C0, N2T);

    f2bf_kernel<<<cdiv(R_NUM * N2T * HC0, 256), 256>>>(z0, z0bf,
                                                       (size_t)R_NUM * N2T * HC0);
    {
        dim3 grid(cdiv(HC0, TBN), cdiv(N2T, TBM), 3 * R_NUM);
        gemm_qkv_tc_kernel<<<grid, 256>>>(
            z0bf, (size_t)N2T * HC0,
            wq0t, wk0t, wv0t, (size_t)HC0 * HC0,
            q0, k0, v0, (size_t)N2T * HC0,
            N2T, HC0, HC0);
    }

    attn_kernel<<<cdiv(N2T * H0 * 32, 256), 256>>>(
        q0, k0, v0, Wrel0, x1, N2T, H0, C0, /*relu=*/1);

    f2bf_kernel<<<cdiv(N2T * HC0, 256), 256>>>(x1, x1bf, (size_t)N2T * HC0);

    // ---- layer 1 ----
    tc_gemm(x1bf, wj1t, nullptr, hj1, N2T, HC1, HC0);
    tc_gemm(x1bf, wi1t, nullptr, hi1, N2T, HC1, HC0);
    tc_gemm(x1bf, sw1t, sb1,     o1,  N2T, HC1, HC0);

    cudaMemsetAsync(den1, 0, (size_t)N2T * R_NUM * H1 * sizeof(float), 0);
    cudaMemsetAsync(z1,   0, (size_t)R_NUM * N2T * HC1 * sizeof(float), 0);

    edge_alpha_kernel<<<cdiv(E1 * 32, 256), 256>>>(
        ei1, ei1 + E1, et1, hj1, hi1, attj1, atti1, exa1, den1, E1, H1, C1);
    edge_scatter_kernel<<<cdiv(E1 * 32, 256), 256>>>(
        ei1, ei1 + E1, et1, hj1, exa1, den1, z1, E1, N2T, H1, C1, N2T);

    for (int r = 0; r < R_NUM; r++) {
        size_t zo = (size_t)r * N2T * HC1;
        size_t wo = (size_t)r * HC1 * HC1;
        dim3 grid(cdiv(HC1, 64), cdiv(N2T, 64));
        gemm_kernel<<<grid, dim3(16, 16)>>>(z1 + zo, Wq1 + wo, q1 + zo, N2T, HC1, HC1);
        gemm_kernel<<<grid, dim3(16, 16)>>>(z1 + zo, Wk1 + wo, k1 + zo, N2T, HC1, HC1);
        gemm_kernel<<<grid, dim3(16, 16)>>>(z1 + zo, Wv1 + wo, v1 + zo, N2T, HC1, HC1);
    }

    attn_kernel<<<cdiv(N2T * H1 * 32, 256), 256>>>(
        q1, k1, v1, Wrel1, o1, N2T, H1, C1, /*relu=*/0);

    // ---- output ----
    log_softmax_kernel<<<cdiv(N2T * 32, 256), 256>>>(o1, (float*)d_out, N2T, C1);
}

// round 4
// speedup vs baseline: 8.0564x; 1.7913x over previous
#include <cuda_runtime.h>
#include <cuda_bf16.h>
#include <math.h>

// ---------------- problem constants ----------------
#define R_NUM 5
#define N1T   30000
#define N2T   15000
#define IN_DIM 128
#define HC0   256
#define H0    4
#define C0    64
#define HC1   40
#define C1    40
#define E0MAX 300000
#define E1MAX 150000

// ---------------- scratch ----------------
__device__ __nv_bfloat16 g_xbf [(size_t)N1T * IN_DIM];
__device__ float g_hj0 [(size_t)N1T * HC0];
__device__ float g_h0all[(size_t)N2T * 512];              // [hi0 | x1self+bias]
__device__ float g_den0[(size_t)N2T * R_NUM * H0];
__device__ __nv_bfloat16 g_z0bf[(size_t)R_NUM * N2T * HC0];
__device__ float g_qkv0[(size_t)3 * R_NUM * N2T * HC0];   // q|k|v each [R][N2T][256]
__device__ __nv_bfloat16 g_x1bf[(size_t)N2T * HC0];
__device__ float g_h1all[(size_t)N2T * 120];              // [hj1 | hi1 | o1self+bias]
__device__ float g_den1[(size_t)N2T * R_NUM];
__device__ __nv_bfloat16 g_z1bf[(size_t)R_NUM * N2T * HC1];
__device__ __nv_bfloat16 g_z1p [(size_t)R_NUM * N2T * 64];
__device__ float g_qkv1[(size_t)R_NUM * N2T * 120];
// weights (transposed / packed, bf16)
__device__ __nv_bfloat16 g_wj0t  [(size_t)HC0 * IN_DIM];
__device__ __nv_bfloat16 g_w0pack[(size_t)512 * IN_DIM];
__device__ float         g_b0pack[512];
__device__ __nv_bfloat16 g_wqkv0t[(size_t)3 * R_NUM * HC0 * HC0];
__device__ __nv_bfloat16 g_w1pack[(size_t)120 * HC0];
__device__ float         g_b1pack[120];
__device__ __nv_bfloat16 g_wqkv1t[(size_t)R_NUM * 120 * 64];

static inline int cdiv(int a, int b) { return (a + b - 1) / b; }

// ---------------- cp.async helpers ----------------
__device__ __forceinline__ void cp16(void* dst, const void* src, bool ok) {
    unsigned d = (unsigned)__cvta_generic_to_shared(dst);
    int n = ok ? 16 : 0;
    asm volatile("cp.async.cg.shared.global [%0], [%1], 16, %2;\n"
                 :: "r"(d), "l"(src), "r"(n));
}
__device__ __forceinline__ void cp_commit() {
    asm volatile("cp.async.commit_group;\n");
}
template <int N> __device__ __forceinline__ void cp_wait() {
    asm volatile("cp.async.wait_group %0;\n" :: "n"(N));
}

// ---------------- bf16 tensor-core GEMM ----------------
__device__ __forceinline__ void mma16816(float* d, const unsigned* a,
                                         const unsigned* b, const float* c)
{
    asm volatile(
        "mma.sync.aligned.m16n8k16.row.col.f32.bf16.bf16.f32 "
        "{%0,%1,%2,%3}, {%4,%5,%6,%7}, {%8,%9}, {%10,%11,%12,%13};\n"
        : "=f"(d[0]), "=f"(d[1]), "=f"(d[2]), "=f"(d[3])
        : "r"(a[0]), "r"(a[1]), "r"(a[2]), "r"(a[3]),
          "r"(b[0]), "r"(b[1]),
          "f"(c[0]), "f"(c[1]), "f"(c[2]), "f"(c[3]));
}

#define TBM 128
#define TBN 128
#define TBK 32
#define TLD 40

// C[M,N](f32) = A[M,K](bf16 rm) @ Bt[N,K](bf16) (+bias). 2-stage cp.async pipeline.
__device__ __forceinline__ void gemm_tc_body(const __nv_bfloat16* __restrict__ A,
                                             const __nv_bfloat16* __restrict__ Bt,
                                             const float* __restrict__ bias,
                                             float* __restrict__ C,
                                             int M, int N, int K)
{
    __shared__ __nv_bfloat16 As[2][TBM * TLD];
    __shared__ __nv_bfloat16 Bs[2][TBN * TLD];
    int tid = threadIdx.x;
    int wid = tid >> 5, lane = tid & 31;
    int wm = wid >> 1, wn = wid & 1;
    int m0 = blockIdx.y * TBM, n0 = blockIdx.x * TBN;
    int g = lane >> 2, cq = lane & 3;
    int r0 = tid >> 2, kg = (tid & 3) * 8;

    float acc[2][8][4];
#pragma unroll
    for (int i = 0; i < 2; i++)
#pragma unroll
        for (int j = 0; j < 8; j++)
#pragma unroll
            for (int q = 0; q < 4; q++) acc[i][j][q] = 0.f;

    int nt = K >> 5;

    // stage loader
    auto load_stage = [&](int s, int kt) {
#pragma unroll
        for (int it = 0; it < 2; it++) {
            int r = r0 + it * 64;
            bool okA = (m0 + r) < M;
            bool okB = (n0 + r) < N;
            const __nv_bfloat16* pa = A + (size_t)(okA ? (m0 + r) : 0) * K + kt + kg;
            const __nv_bfloat16* pb = Bt + (size_t)(okB ? (n0 + r) : 0) * K + kt + kg;
            cp16(&As[s][r * TLD + kg], pa, okA);
            cp16(&Bs[s][r * TLD + kg], pb, okB);
        }
        cp_commit();
    };

    load_stage(0, 0);

    for (int i = 0; i < nt; i++) {
        if (i + 1 < nt) { load_stage((i + 1) & 1, (i + 1) << 5); cp_wait<1>(); }
        else            { cp_wait<0>(); }
        __syncthreads();
        int s = i & 1;
#pragma unroll
        for (int ks = 0; ks < 2; ks++) {
            int kb = ks * 16;
            unsigned a[2][4], b[8][2];
#pragma unroll
            for (int mf = 0; mf < 2; mf++) {
                const __nv_bfloat16* p = &As[s][(wm * 32 + mf * 16 + g) * TLD + kb + cq * 2];
                a[mf][0] = *reinterpret_cast<const unsigned*>(p);
                a[mf][1] = *reinterpret_cast<const unsigned*>(p + 8 * TLD);
                a[mf][2] = *reinterpret_cast<const unsigned*>(p + 8);
                a[mf][3] = *reinterpret_cast<const unsigned*>(p + 8 * TLD + 8);
            }
#pragma unroll
            for (int nf = 0; nf < 8; nf++) {
                const __nv_bfloat16* p = &Bs[s][(wn * 64 + nf * 8 + g) * TLD + kb + cq * 2];
                b[nf][0] = *reinterpret_cast<const unsigned*>(p);
                b[nf][1] = *reinterpret_cast<const unsigned*>(p + 8);
            }
#pragma unroll
            for (int mf = 0; mf < 2; mf++)
#pragma unroll
                for (int nf = 0; nf < 8; nf++)
                    mma16816(acc[mf][nf], a[mf], b[nf], acc[mf][nf]);
        }
        __syncthreads();
    }

#pragma unroll
    for (int mf = 0; mf < 2; mf++) {
#pragma unroll
        for (int nf = 0; nf < 8; nf++) {
            int col = n0 + wn * 64 + nf * 8 + cq * 2;
            int row = m0 + wm * 32 + mf * 16 + g;
            if (col >= N) continue;
            float b0 = 0.f, b1 = 0.f;
            if (bias) { b0 = bias[col]; b1 = bias[col + 1]; }
            if (row < M) {
                float2 v = make_float2(acc[mf][nf][0] + b0, acc[mf][nf][1] + b1);
                *reinterpret_cast<float2*>(C + (size_t)row * N + col) = v;
            }
            if (row + 8 < M) {
                float2 v = make_float2(acc[mf][nf][2] + b0, acc[mf][nf][3] + b1);
                *reinterpret_cast<float2*>(C + (size_t)(row + 8) * N + col) = v;
            }
        }
    }
}

__global__ void gemm_tc_kernel(const __nv_bfloat16* __restrict__ A,
                               const __nv_bfloat16* __restrict__ Bt,
                               const float* __restrict__ bias,
                               float* __restrict__ C, int M, int N, int K)
{
    gemm_tc_body(A, Bt, bias, C, M, N, K);
}

__global__ void gemm_tc_batch(const __nv_bfloat16* __restrict__ A, size_t sA,
                              const __nv_bfloat16* __restrict__ Bt, size_t sB,
                              float* __restrict__ C, size_t sC,
                              int M, int N, int K)
{
    int r = blockIdx.z;
    gemm_tc_body(A + (size_t)r * sA, Bt + (size_t)r * sB, nullptr,
                 C + (size_t)r * sC, M, N, K);
}

// qkv0: A is shared per relation r; z = which*5 + r (q block, k block, v block)
__global__ void gemm_tc_qkv0(const __nv_bfloat16* __restrict__ A, size_t sA,
                             const __nv_bfloat16* __restrict__ Bt, size_t sB,
                             float* __restrict__ C, size_t sC,
                             int M, int N, int K)
{
    int z = blockIdx.z;
    int r = z % R_NUM;
    gemm_tc_body(A + (size_t)r * sA, Bt + (size_t)z * sB, nullptr,
                 C + (size_t)z * sC, M, N, K);
}

// ---------------- prep kernels ----------------
__global__ void gather_bf(const float* __restrict__ emb,
                          const int* __restrict__ n_id,
                          const int* __restrict__ lni,
                          __nv_bfloat16* __restrict__ xbf)
{
    int i = blockIdx.x * blockDim.x + threadIdx.x;
    if (i >= N1T * 32) return;
    int n = i >> 5, d = i & 31;
    int row = lni[n_id[n]];
    float4 v = reinterpret_cast<const float4*>(emb)[(size_t)row * 32 + d];
    __nv_bfloat162 lo = __floats2bfloat162_rn(v.x, v.y);
    __nv_bfloat162 hi = __floats2bfloat162_rn(v.z, v.w);
    uint2 pk;
    pk.x = *reinterpret_cast<unsigned*>(&lo);
    pk.y = *reinterpret_cast<unsigned*>(&hi);
    reinterpret_cast<uint2*>(xbf)[(size_t)n * 32 + d] = pk;
}

// z0: Wj0 -> wj0t; z1: Wi0 -> w0pack[0:256]; z2: sw0 -> w0pack[256:512] (+bias pad)
__global__ void prep0(const float* __restrict__ Wj0, const float* __restrict__ Wi0,
                      const float* __restrict__ sw0, const float* __restrict__ sb0,
                      __nv_bfloat16* __restrict__ wj0t, __nv_bfloat16* __restrict__ w0pack,
                      float* __restrict__ b0pack)
{
    int i = blockIdx.x * 256 + threadIdx.x;
    int z = blockIdx.y;
    if (i >= IN_DIM * HC0) return;
    int k = i >> 8, n = i & 255;
    const float* src = (z == 0) ? Wj0 : (z == 1) ? Wi0 : sw0;
    __nv_bfloat16 v = __float2bfloat16(src[i]);
    if (z == 0) {
        wj0t[(size_t)n * IN_DIM + k] = v;
        if (i < 256) b0pack[i] = 0.f;
    } else {
        int off = (z == 2) ? 256 : 0;
        w0pack[((size_t)(off + n)) * IN_DIM + k] = v;
        if (z == 2 && i < 256) b0pack[256 + i] = sb0[i];
    }
}

// z = which*5 + r : W(which)[r] (256x256) -> wqkv0t[z] transposed
__global__ void prepQKV0(const float* __restrict__ Wq, const float* __restrict__ Wk,
                         const float* __restrict__ Wv, __nv_bfloat16* __restrict__ dst)
{
    int i = blockIdx.x * 256 + threadIdx.x;
    int z = blockIdx.y;
    if (i >= HC0 * HC0) return;
    int which = z / R_NUM, r = z % R_NUM;
    const float* src = ((which == 0) ? Wq : (which == 1) ? Wk : Wv) + (size_t)r * HC0 * HC0;
    int k = i >> 8, n = i & 255;
    dst[(size_t)z * HC0 * HC0 + (size_t)n * HC0 + k] = __float2bfloat16(src[i]);
}

// z: Wj1/Wi1/sw1 [256][40] -> w1pack rows z*40+col, and bias pad
__global__ void prep1(const float* __restrict__ Wj1, const float* __restrict__ Wi1,
                      const float* __restrict__ sw1, const float* __restrict__ sb1,
                      __nv_bfloat16* __restrict__ w1pack, float* __restrict__ b1pack)
{
    int i = blockIdx.x * 256 + threadIdx.x;
    int z = blockIdx.y;
    if (i >= HC0 * C1) return;
    int k = i / C1, col = i - k * C1;
    const float* src = (z == 0) ? Wj1 : (z == 1) ? Wi1 : sw1;
    w1pack[(size_t)(z * C1 + col) * HC0 + k] = __float2bfloat16(src[i]);
    if (z == 0 && i < 80) b1pack[i] = 0.f;
    if (z == 2 && i < C1) b1pack[80 + i] = sb1[i];
}

// wqkv1t [r][120][64]: n = which*40+col, k padded to 64
__global__ void prepQKV1(const float* __restrict__ Wq, const float* __restrict__ Wk,
                         const float* __restrict__ Wv, __nv_bfloat16* __restrict__ dst)
{
    int i = blockIdx.x * 256 + threadIdx.x;
    int r = blockIdx.y;
    if (i >= 120 * 64) return;
    int n = i >> 6, k = i & 63;
    int which = n / C1, col = n - which * C1;
    float v = 0.f;
    if (k < C1) {
        const float* src = ((which == 0) ? Wq : (which == 1) ? Wk : Wv) + (size_t)r * C1 * C1;
        v = src[k * C1 + col];
    }
    dst[(size_t)r * 120 * 64 + i] = __float2bfloat16(v);
}

// ---------------- fused edge kernels (unnormalized scatter) ----------------
__global__ void edge_fused0(const int* __restrict__ src, const int* __restrict__ tgt,
                            const int* __restrict__ et,
                            const float* __restrict__ hj,     // [N1T][256]
                            const float* __restrict__ hall,   // hi0 = rows stride 512
                            const float* __restrict__ attj, const float* __restrict__ atti,
                            float* __restrict__ den, __nv_bfloat162* __restrict__ z,
                            int E)
{
    int w = (blockIdx.x * blockDim.x + threadIdx.x) >> 5;
    int lane = threadIdx.x & 31;
    if (w >= E) return;
    int gn = tgt[w];
    if (gn >= N2T) return;
    int t = et[w], s = src[w];
    const float* hjr = hj + (size_t)s * 256;
    const float* hir = hall + (size_t)gn * 512;
    int h = lane >> 3, j = lane & 7;
    const float* ajh = attj + ((size_t)t * 4 + h) * 64;
    const float* aih = atti + ((size_t)t * 4 + h) * 64;
    float acc = 0.f;
#pragma unroll
    for (int u = 0; u < 8; u++) {
        int c = j + 8 * u;
        acc += ajh[c] * hjr[h * 64 + c] + aih[c] * hir[h * 64 + c];
    }
#pragma unroll
    for (int o = 4; o; o >>= 1) acc += __shfl_xor_sync(0xffffffffu, acc, o);
    float a = acc >= 0.f ? acc : 0.2f * acc;
    float ex = expf(a);
    if (j == 0) atomicAdd(&den[((size_t)gn * R_NUM + t) * 4 + h], ex);
    float exh[4];
#pragma unroll
    for (int hh = 0; hh < 4; hh++) exh[hh] = __shfl_sync(0xffffffffu, ex, hh * 8);
    __nv_bfloat162* zr = z + ((size_t)t * N2T + gn) * 128;
#pragma unroll
    for (int u = 0; u < 4; u++) {
        int c2 = lane + 32 * u;                       // pair index; head = u
        float e = exh[u];
        __nv_bfloat162 val = __floats2bfloat162_rn(e * hjr[2 * c2], e * hjr[2 * c2 + 1]);
        atomicAdd(&zr[c2], val);
    }
}

__global__ void edge_fused1(const int* __restrict__ src, const int* __restrict__ tgt,
                            const int* __restrict__ et,
                            const float* __restrict__ hall,   // [N2T][120]: hj=0..39, hi=40..79
                            const float* __restrict__ attj, const float* __restrict__ atti,
                            float* __restrict__ den, __nv_bfloat162* __restrict__ z,
                            int E)
{
    int w = (blockIdx.x * blockDim.x + threadIdx.x) >> 5;
    int lane = threadIdx.x & 31;
    if (w >= E) return;
    int gn = tgt[w];
    int t = et[w], s = src[w];
    const float* hjr = hall + (size_t)s * 120;
    const float* hir = hall + (size_t)gn * 120 + 40;
    const float* aj = attj + (size_t)t * 40;
    const float* ai = atti + (size_t)t * 40;
    float acc = 0.f;
    if (lane < 40) {}   // lanes 0..31 always valid for c0
    acc += aj[lane] * hjr[lane] + ai[lane] * hir[lane];
    if (lane < 8) acc += aj[lane + 32] * hjr[lane + 32] + ai[lane + 32] * hir[lane + 32];
#pragma unroll
    for (int o = 16; o; o >>= 1) acc += __shfl_xor_sync(0xffffffffu, acc, o);
    float a = acc >= 0.f ? acc : 0.2f * acc;
    float ex = expf(a);
    if (lane == 0) atomicAdd(&den[(size_t)gn * R_NUM + t], ex);
    __nv_bfloat162* zr = z + ((size_t)t * N2T + gn) * 20;
    if (lane < 20) {
        __nv_bfloat162 val = __floats2bfloat162_rn(ex * hjr[2 * lane], ex * hjr[2 * lane + 1]);
        atomicAdd(&zr[lane], val);
    }
}

// ---------------- normalize / pad ----------------
__global__ void z0_norm(__nv_bfloat162* __restrict__ z, const float* __restrict__ den)
{
    size_t i = (size_t)blockIdx.x * 256 + threadIdx.x;
    const size_t tot = (size_t)R_NUM * N2T * 128;
    if (i >= tot) return;
    int c2 = i & 127;
    size_t row = i >> 7;
    int r = row / N2T; int n = (int)(row - (size_t)r * N2T);
    int h = c2 >> 5;
    float d = fmaxf(den[((size_t)n * R_NUM + r) * 4 + h], 1e-16f);
    float inv = __fdividef(1.f, d);
    __nv_bfloat162 v = z[i];
    z[i] = __floats2bfloat162_rn(__low2float(v) * inv, __high2float(v) * inv);
}

__global__ void z1_pad(const __nv_bfloat16* __restrict__ z, const float* __restrict__ den,
                       __nv_bfloat16* __restrict__ out)
{
    int i = blockIdx.x * 256 + threadIdx.x;
    const int tot = R_NUM * N2T * 64;
    if (i >= tot) return;
    int c = i & 63;
    int row = i >> 6;
    int r = row / N2T; int n = row - r * N2T;
    float v = 0.f;
    if (c < 40) {
        float inv = __fdividef(1.f, fmaxf(den[(size_t)n * R_NUM + r], 1e-16f));
        v = __bfloat162float(z[(size_t)row * 40 + c]) * inv;
    }
    out[i] = __float2bfloat16(v);
}

// ---------------- bilevel relation attention ----------------
__device__ __forceinline__ void relcoeff(const float psi[R_NUM][R_NUM],
                                         const float* wrel, float coeff[R_NUM])
{
#pragma unroll
    for (int s = 0; s < R_NUM; s++) coeff[s] = 0.f;
#pragma unroll
    for (int r = 0; r < R_NUM; r++) {
        float rsum = 0.f;
#pragma unroll
        for (int s = 0; s < R_NUM; s++) rsum += psi[r][s];
        float pv[R_NUM], mx = -INFINITY;
#pragma unroll
        for (int s = 0; s < R_NUM; s++) {
            float xx = psi[r][s];
            bool masked = (xx == 0.f) && (rsum != 0.f);
            pv[s] = masked ? -INFINITY : xx;
            mx = fmaxf(mx, pv[s]);
        }
        float pe[R_NUM], se = 0.f;
#pragma unroll
        for (int s = 0; s < R_NUM; s++) {
            float e = isinf(pv[s]) ? 0.f : expf(pv[s] - mx);
            pe[s] = e; se += e;
        }
        float inv = wrel[r] / se;
#pragma unroll
        for (int s = 0; s < R_NUM; s++) coeff[s] += pe[s] * inv;
    }
}

// layer0: warp per (n,h). q/k/v [R][N2T][256]; self from h0all cols 256.. ; out bf16 + relu
__global__ void attn0_kernel(const float* __restrict__ q, const float* __restrict__ k,
                             const float* __restrict__ v, const float* __restrict__ wrel,
                             const float* __restrict__ hall, __nv_bfloat16* __restrict__ outbf)
{
    int w = (blockIdx.x * blockDim.x + threadIdx.x) >> 5;
    int lane = threadIdx.x & 31;
    if (w >= N2T * 4) return;
    int n = w >> 2, h = w & 3;
    size_t base = (size_t)n * 256 + h * 64;
    const size_t rst = (size_t)N2T * 256;
    int c0 = lane, c1 = lane + 32;

    float qv[R_NUM][2], kv[R_NUM][2], vv[R_NUM][2];
#pragma unroll
    for (int r = 0; r < R_NUM; r++) {
        size_t o = (size_t)r * rst + base;
        qv[r][0] = q[o + c0]; qv[r][1] = q[o + c1];
        kv[r][0] = k[o + c0]; kv[r][1] = k[o + c1];
        vv[r][0] = v[o + c0]; vv[r][1] = v[o + c1];
    }
    float psi[R_NUM][R_NUM];
#pragma unroll
    for (int r = 0; r < R_NUM; r++)
#pragma unroll
        for (int s = 0; s < R_NUM; s++) {
            float p = qv[r][0] * kv[s][0] + qv[r][1] * kv[s][1];
#pragma unroll
            for (int o = 16; o; o >>= 1) p += __shfl_xor_sync(0xffffffffu, p, o);
            psi[r][s] = p;
        }
    float coeff[R_NUM];
    relcoeff(psi, wrel, coeff);

    const float* self = hall + (size_t)n * 512 + 256 + h * 64;
#pragma unroll
    for (int jj = 0; jj < 2; jj++) {
        int c = lane + 32 * jj;
        float acc = 0.f;
#pragma unroll
        for (int s = 0; s < R_NUM; s++) acc += coeff[s] * vv[s][jj];
        float val = self[c] + acc;
        outbf[base + c] = __float2bfloat16(fmaxf(val, 0.f));
    }
}

// layer1: warp per node. qkv [R][N2T][120]; self = h1all cols 80..119; fused log_softmax
__global__ void attn1_ls(const float* __restrict__ qkv, const float* __restrict__ wrel,
                         const float* __restrict__ hall, float* __restrict__ out)
{
    int w = (blockIdx.x * blockDim.x + threadIdx.x) >> 5;
    int lane = threadIdx.x & 31;
    if (w >= N2T) return;
    int n = w;
    const size_t rst = (size_t)N2T * 120;
    size_t base = (size_t)n * 120;
    bool ok1 = lane < 8;

    float qv[R_NUM][2], kv[R_NUM][2], vv[R_NUM][2];
#pragma unroll
    for (int r = 0; r < R_NUM; r++) {
        const float* p = qkv + (size_t)r * rst + base;
        qv[r][0] = p[lane];      qv[r][1] = ok1 ? p[32 + lane] : 0.f;
        kv[r][0] = p[40 + lane]; kv[r][1] = ok1 ? p[72 + lane] : 0.f;
        vv[r][0] = p[80 + lane]; vv[r][1] = ok1 ? p[112 + lane] : 0.f;
    }
    float psi[R_NUM][R_NUM];
#pragma unroll
    for (int r = 0; r < R_NUM; r++)
#pragma unroll
        for (int s = 0; s < R_NUM; s++) {
            float p = qv[r][0] * kv[s][0] + qv[r][1] * kv[s][1];
#pragma unroll
            for (int o = 16; o; o >>= 1) p += __shfl_xor_sync(0xffffffffu, p, o);
            psi[r][s] = p;
        }
    float coeff[R_NUM];
    relcoeff(psi, wrel, coeff);

    const float* self = hall + (size_t)n * 120 + 80;
    float a0 = 0.f, a1 = 0.f;
#pragma unroll
    for (int s = 0; s < R_NUM; s++) { a0 += coeff[s] * vv[s][0]; a1 += coeff[s] * vv[s][1]; }
    float v0 = self[lane] + a0;
    float v1 = ok1 ? self[32 + lane] + a1 : -INFINITY;

    float mx = fmaxf(v0, v1);
#pragma unroll
    for (int o = 16; o; o >>= 1) mx = fmaxf(mx, __shfl_xor_sync(0xffffffffu, mx, o));
    float se = expf(v0 - mx) + (ok1 ? expf(v1 - mx) : 0.f);
#pragma unroll
    for (int o = 16; o; o >>= 1) se += __shfl_xor_sync(0xffffffffu, se, o);
    float lse = mx + logf(se);
    out[(size_t)n * 40 + lane] = v0 - lse;
    if (ok1) out[(size_t)n * 40 + 32 + lane] = v1 - lse;
}

// ---------------- host ----------------
extern "C" void kernel_launch(void* const* d_in, const int* in_sizes, int n_in,
                              void* d_out, int out_size)
{
    const int*   n_id  = (const int*)d_in[0];
    const int*   lni   = (const int*)d_in[1];
    const int*   ei0   = (const int*)d_in[3];
    const int*   et0   = (const int*)d_in[4];
    const int*   ei1   = (const int*)d_in[5];
    const int*   et1   = (const int*)d_in[6];
    const float* emb   = (const float*)d_in[7];
    const float* Wj0   = (const float*)d_in[8];
    const float* Wi0   = (const float*)d_in[9];
    const float* attj0 = (const float*)d_in[10];
    const float* atti0 = (const float*)d_in[11];
    const float* Wq0   = (const float*)d_in[12];
    const float* Wk0   = (const float*)d_in[13];
    const float* Wv0   = (const float*)d_in[14];
    const float* sw0   = (const float*)d_in[15];
    const float* sb0   = (const float*)d_in[16];
    const float* Wrel0 = (const float*)d_in[17];
    const float* Wj1   = (const float*)d_in[18];
    const float* Wi1   = (const float*)d_in[19];
    const float* attj1 = (const float*)d_in[20];
    const float* atti1 = (const float*)d_in[21];
    const float* Wq1   = (const float*)d_in[22];
    const float* Wk1   = (const float*)d_in[23];
    const float* Wv1   = (const float*)d_in[24];
    const float* sw1   = (const float*)d_in[25];
    const float* sb1   = (const float*)d_in[26];
    const float* Wrel1 = (const float*)d_in[27];

    int E0 = in_sizes[4];
    int E1 = in_sizes[6];

    __nv_bfloat16 *xbf, *z0bf, *x1bf, *z1bf, *z1p;
    __nv_bfloat16 *wj0t, *w0pack, *wqkv0t, *w1pack, *wqkv1t;
    float *hj0, *h0all, *den0, *qkv0, *h1all, *den1, *qkv1, *b0pack, *b1pack;
    cudaGetSymbolAddress((void**)&xbf,    g_xbf);
    cudaGetSymbolAddress((void**)&hj0,    g_hj0);
    cudaGetSymbolAddress((void**)&h0all,  g_h0all);
    cudaGetSymbolAddress((void**)&den0,   g_den0);
    cudaGetSymbolAddress((void**)&z0bf,   g_z0bf);
    cudaGetSymbolAddress((void**)&qkv0,   g_qkv0);
    cudaGetSymbolAddress((void**)&x1bf,   g_x1bf);
    cudaGetSymbolAddress((void**)&h1all,  g_h1all);
    cudaGetSymbolAddress((void**)&den1,   g_den1);
    cudaGetSymbolAddress((void**)&z1bf,   g_z1bf);
    cudaGetSymbolAddress((void**)&z1p,    g_z1p);
    cudaGetSymbolAddress((void**)&qkv1,   g_qkv1);
    cudaGetSymbolAddress((void**)&wj0t,   g_wj0t);
    cudaGetSymbolAddress((void**)&w0pack, g_w0pack);
    cudaGetSymbolAddress((void**)&b0pack, g_b0pack);
    cudaGetSymbolAddress((void**)&wqkv0t, g_wqkv0t);
    cudaGetSymbolAddress((void**)&w1pack, g_w1pack);
    cudaGetSymbolAddress((void**)&b1pack, g_b1pack);
    cudaGetSymbolAddress((void**)&wqkv1t, g_wqkv1t);

    // ---- prep ----
    gather_bf<<<cdiv(N1T * 32, 256), 256>>>(emb, n_id, lni, xbf);
    prep0<<<dim3(cdiv(IN_DIM * HC0, 256), 3), 256>>>(Wj0, Wi0, sw0, sb0, wj0t, w0pack, b0pack);
    prepQKV0<<<dim3(cdiv(HC0 * HC0, 256), 15), 256>>>(Wq0, Wk0, Wv0, wqkv0t);
    prep1<<<dim3(cdiv(HC0 * C1, 256), 3), 256>>>(Wj1, Wi1, sw1, sb1, w1pack, b1pack);
    prepQKV1<<<dim3(cdiv(120 * 64, 256), R_NUM), 256>>>(Wq1, Wk1, Wv1, wqkv1t);

    cudaMemsetAsync(den0, 0, (size_t)N2T * R_NUM * H0 * sizeof(float), 0);
    cudaMemsetAsync(z0bf, 0, (size_t)R_NUM * N2T * HC0 * sizeof(__nv_bfloat16), 0);
    cudaMemsetAsync(den1, 0, (size_t)N2T * R_NUM * sizeof(float), 0);
    cudaMemsetAsync(z1bf, 0, (size_t)R_NUM * N2T * HC1 * sizeof(__nv_bfloat16), 0);

    // ---- layer 0 ----
    gemm_tc_kernel<<<dim3(2, cdiv(N1T, TBM)), 256>>>(xbf, wj0t, nullptr, hj0, N1T, 256, IN_DIM);
    gemm_tc_kernel<<<dim3(4, cdiv(N2T, TBM)), 256>>>(xbf, w0pack, b0pack, h0all, N2T, 512, IN_DIM);

    edge_fused0<<<cdiv(E0 * 32, 256), 256>>>(ei0, ei0 + E0, et0, hj0, h0all,
                                             attj0, atti0, den0,
                                             (__nv_bfloat162*)z0bf, E0);
    z0_norm<<<cdiv(R_NUM * N2T * 128, 256), 256>>>((__nv_bfloat162*)z0bf, den0);

    gemm_tc_qkv0<<<dim3(2, cdiv(N2T, TBM), 15), 256>>>(
        z0bf, (size_t)N2T * HC0,
        wqkv0t, (size_t)HC0 * HC0,
        qkv0, (size_t)N2T * HC0,
        N2T, HC0, HC0);

    {
        const float* q0 = qkv0;
        const float* k0 = qkv0 + (size_t)R_NUM * N2T * HC0;
        const float* v0 = qkv0 + (size_t)2 * R_NUM * N2T * HC0;
        attn0_kernel<<<cdiv(N2T * 4 * 32, 256), 256>>>(q0, k0, v0, Wrel0, h0all, x1bf);
    }

    // ---- layer 1 ----
    gemm_tc_kernel<<<dim3(1, cdiv(N2T, TBM)), 256>>>(x1bf, w1pack, b1pack, h1all, N2T, 120, HC0);

    edge_fused1<<<cdiv(E1 * 32, 256), 256>>>(ei1, ei1 + E1, et1, h1all,
                                             attj1, atti1, den1,
                                             (__nv_bfloat162*)z1bf, E1);
    z1_pad<<<cdiv(R_NUM * N2T * 64, 256), 256>>>(z1bf, den1, z1p);

    gemm_tc_batch<<<dim3(1, cdiv(N2T, TBM), R_NUM), 256>>>(
        z1p, (size_t)N2T * 64,
        wqkv1t, (size_t)120 * 64,
        qkv1, (size_t)N2T * 120,
        N2T, 120, 64);

    attn1_ls<<<cdiv(N2T * 32, 256), 256>>>(qkv1, Wrel1, h1all, (float*)d_out);
}

// round 5
// speedup vs baseline: 8.3909x; 1.0415x over previous
#include <cuda_runtime.h>
#include <cuda_bf16.h>
#include <math.h>

// ---------------- problem constants ----------------
#define R_NUM 5
#define N1T   30000
#define N2T   15000
#define IN_DIM 128
#define HC0   256
#define H0    4
#define C0    64
#define HC1   40
#define C1    40
#define E0MAX 300000
#define E1MAX 150000

// ---------------- scratch ----------------
__device__ __nv_bfloat16 g_xbf [(size_t)N1T * IN_DIM];
__device__ float g_hj0 [(size_t)N1T * HC0];
__device__ float g_h0all[(size_t)N2T * 512];              // [hi0 | x1self+bias]
__device__ float g_den0[(size_t)N2T * R_NUM * H0];
__device__ __nv_bfloat16 g_z0bf[(size_t)R_NUM * N2T * HC0];
__device__ __nv_bfloat16 g_qkv0bf[(size_t)3 * R_NUM * N2T * HC0]; // q|k|v
__device__ __nv_bfloat16 g_x1bf[(size_t)N2T * HC0];
__device__ float g_h1all[(size_t)N2T * 120];              // [hj1 | hi1 | o1self+bias]
__device__ float g_den1[(size_t)N2T * R_NUM];
__device__ __nv_bfloat16 g_z1bf[(size_t)R_NUM * N2T * HC1];
__device__ __nv_bfloat16 g_z1p [(size_t)R_NUM * N2T * 64];
__device__ float g_qkv1[(size_t)R_NUM * N2T * 120];
// weights (transposed / packed, bf16)
__device__ __nv_bfloat16 g_wj0t  [(size_t)HC0 * IN_DIM];
__device__ __nv_bfloat16 g_w0pack[(size_t)512 * IN_DIM];
__device__ float         g_b0pack[512];
__device__ __nv_bfloat16 g_wqkv0t[(size_t)3 * R_NUM * HC0 * HC0];
__device__ __nv_bfloat16 g_w1pack[(size_t)120 * HC0];
__device__ float         g_b1pack[120];
__device__ __nv_bfloat16 g_wqkv1t[(size_t)R_NUM * 120 * 64];

static inline int cdiv(int a, int b) { return (a + b - 1) / b; }

// ---------------- cp.async helpers ----------------
__device__ __forceinline__ void cp16(void* dst, const void* src, bool ok) {
    unsigned d = (unsigned)__cvta_generic_to_shared(dst);
    int n = ok ? 16 : 0;
    asm volatile("cp.async.cg.shared.global [%0], [%1], 16, %2;\n"
                 :: "r"(d), "l"(src), "r"(n));
}
__device__ __forceinline__ void cp_commit() {
    asm volatile("cp.async.commit_group;\n");
}
template <int N> __device__ __forceinline__ void cp_wait() {
    asm volatile("cp.async.wait_group %0;\n" :: "n"(N));
}

// ---------------- bf16 tensor-core GEMM ----------------
__device__ __forceinline__ void mma16816(float* d, const unsigned* a,
                                         const unsigned* b, const float* c)
{
    asm volatile(
        "mma.sync.aligned.m16n8k16.row.col.f32.bf16.bf16.f32 "
        "{%0,%1,%2,%3}, {%4,%5,%6,%7}, {%8,%9}, {%10,%11,%12,%13};\n"
        : "=f"(d[0]), "=f"(d[1]), "=f"(d[2]), "=f"(d[3])
        : "r"(a[0]), "r"(a[1]), "r"(a[2]), "r"(a[3]),
          "r"(b[0]), "r"(b[1]),
          "f"(c[0]), "f"(c[1]), "f"(c[2]), "f"(c[3]));
}

#define TBM 128
#define TBN 128
#define TLD 40

// C[M,N] = A[M,K](bf16 rm) @ Bt[N,K](bf16) (+bias). 3-stage cp.async pipeline.
// OT = float or __nv_bfloat16.
template <typename OT>
__device__ __forceinline__ void gemm_tc_body(const __nv_bfloat16* __restrict__ A,
                                             const __nv_bfloat16* __restrict__ Bt,
                                             const float* __restrict__ bias,
                                             OT* __restrict__ C,
                                             int M, int N, int K)
{
    __shared__ __nv_bfloat16 As[3][TBM * TLD];
    __shared__ __nv_bfloat16 Bs[3][TBN * TLD];
    int tid = threadIdx.x;
    int wid = tid >> 5, lane = tid & 31;
    int wm = wid >> 1, wn = wid & 1;
    int m0 = blockIdx.y * TBM, n0 = blockIdx.x * TBN;
    int g = lane >> 2, cq = lane & 3;
    int r0 = tid >> 2, kg = (tid & 3) * 8;

    float acc[2][8][4];
#pragma unroll
    for (int i = 0; i < 2; i++)
#pragma unroll
        for (int j = 0; j < 8; j++)
#pragma unroll
            for (int q = 0; q < 4; q++) acc[i][j][q] = 0.f;

    int nt = K >> 5;

    auto load_stage = [&](int s, int kt, bool active) {
        if (active) {
#pragma unroll
            for (int it = 0; it < 2; it++) {
                int r = r0 + it * 64;
                bool okA = (m0 + r) < M;
                bool okB = (n0 + r) < N;
                const __nv_bfloat16* pa = A + (size_t)(okA ? (m0 + r) : 0) * K + kt + kg;
                const __nv_bfloat16* pb = Bt + (size_t)(okB ? (n0 + r) : 0) * K + kt + kg;
                cp16(&As[s][r * TLD + kg], pa, okA);
                cp16(&Bs[s][r * TLD + kg], pb, okB);
            }
        }
        cp_commit();
    };

    load_stage(0, 0, true);
    load_stage(1, 32, nt > 1);

    for (int i = 0; i < nt; i++) {
        load_stage((i + 2) % 3, (i + 2) << 5, (i + 2) < nt);
        cp_wait<2>();
        __syncthreads();
        int s = i % 3;
#pragma unroll
        for (int ks = 0; ks < 2; ks++) {
            int kb = ks * 16;
            unsigned a[2][4], b[8][2];
#pragma unroll
            for (int mf = 0; mf < 2; mf++) {
                const __nv_bfloat16* p = &As[s][(wm * 32 + mf * 16 + g) * TLD + kb + cq * 2];
                a[mf][0] = *reinterpret_cast<const unsigned*>(p);
                a[mf][1] = *reinterpret_cast<const unsigned*>(p + 8 * TLD);
                a[mf][2] = *reinterpret_cast<const unsigned*>(p + 8);
                a[mf][3] = *reinterpret_cast<const unsigned*>(p + 8 * TLD + 8);
            }
#pragma unroll
            for (int nf = 0; nf < 8; nf++) {
                const __nv_bfloat16* p = &Bs[s][(wn * 64 + nf * 8 + g) * TLD + kb + cq * 2];
                b[nf][0] = *reinterpret_cast<const unsigned*>(p);
                b[nf][1] = *reinterpret_cast<const unsigned*>(p + 8);
            }
#pragma unroll
            for (int mf = 0; mf < 2; mf++)
#pragma unroll
                for (int nf = 0; nf < 8; nf++)
                    mma16816(acc[mf][nf], a[mf], b[nf], acc[mf][nf]);
        }
        __syncthreads();
    }

#pragma unroll
    for (int mf = 0; mf < 2; mf++) {
#pragma unroll
        for (int nf = 0; nf < 8; nf++) {
            int col = n0 + wn * 64 + nf * 8 + cq * 2;
            int row = m0 + wm * 32 + mf * 16 + g;
            if (col >= N) continue;
            float b0 = 0.f, b1 = 0.f;
            if (bias) { b0 = bias[col]; b1 = bias[col + 1]; }
#pragma unroll
            for (int half = 0; half < 2; half++) {
                int rr = row + half * 8;
                if (rr >= M) continue;
                float x0 = acc[mf][nf][half * 2 + 0] + b0;
                float x1 = acc[mf][nf][half * 2 + 1] + b1;
                if constexpr (sizeof(OT) == 2) {
                    __nv_bfloat162 v = __floats2bfloat162_rn(x0, x1);
                    *reinterpret_cast<__nv_bfloat162*>(
                        (__nv_bfloat16*)C + (size_t)rr * N + col) = v;
                } else {
                    *reinterpret_cast<float2*>((float*)C + (size_t)rr * N + col) =
                        make_float2(x0, x1);
                }
            }
        }
    }
}

__global__ void gemm_tc_f32(const __nv_bfloat16* __restrict__ A,
                            const __nv_bfloat16* __restrict__ Bt,
                            const float* __restrict__ bias,
                            float* __restrict__ C, int M, int N, int K)
{
    gemm_tc_body<float>(A, Bt, bias, C, M, N, K);
}

// qkv0: A shared per relation r; z = which*5 + r. bf16 output.
__global__ void gemm_tc_qkv0(const __nv_bfloat16* __restrict__ A, size_t sA,
                             const __nv_bfloat16* __restrict__ Bt, size_t sB,
                             __nv_bfloat16* __restrict__ C, size_t sC,
                             int M, int N, int K)
{
    int z = blockIdx.z;
    int r = z % R_NUM;
    gemm_tc_body<__nv_bfloat16>(A + (size_t)r * sA, Bt + (size_t)z * sB, nullptr,
                                C + (size_t)z * sC, M, N, K);
}

__global__ void gemm_tc_batch_f32(const __nv_bfloat16* __restrict__ A, size_t sA,
                                  const __nv_bfloat16* __restrict__ Bt, size_t sB,
                                  float* __restrict__ C, size_t sC,
                                  int M, int N, int K)
{
    int r = blockIdx.z;
    gemm_tc_body<float>(A + (size_t)r * sA, Bt + (size_t)r * sB, nullptr,
                        C + (size_t)r * sC, M, N, K);
}

// ---------------- gather ----------------
__global__ void gather_bf(const float* __restrict__ emb,
                          const int* __restrict__ n_id,
                          const int* __restrict__ lni,
                          __nv_bfloat16* __restrict__ xbf)
{
    int i = blockIdx.x * blockDim.x + threadIdx.x;
    if (i >= N1T * 32) return;
    int n = i >> 5, d = i & 31;
    int row = lni[n_id[n]];
    float4 v = reinterpret_cast<const float4*>(emb)[(size_t)row * 32 + d];
    __nv_bfloat162 lo = __floats2bfloat162_rn(v.x, v.y);
    __nv_bfloat162 hi = __floats2bfloat162_rn(v.z, v.w);
    uint2 pk;
    pk.x = *reinterpret_cast<unsigned*>(&lo);
    pk.y = *reinterpret_cast<unsigned*>(&hi);
    reinterpret_cast<uint2*>(xbf)[(size_t)n * 32 + d] = pk;
}

// ---------------- mega prep: all weight conversions + zero-fills ----------------
#define B_S0 384
#define B_S1 3840
#define B_S2 120
#define B_S3 150
#define B_S4 293
#define B_S5 9375
#define B_S6 74
#define B_S7 1465
#define B_TOT (B_S0+B_S1+B_S2+B_S3+B_S4+B_S5+B_S6+B_S7)

__global__ void mega_prep(const float* __restrict__ Wj0, const float* __restrict__ Wi0,
                          const float* __restrict__ sw0, const float* __restrict__ sb0,
                          const float* __restrict__ Wq0, const float* __restrict__ Wk0,
                          const float* __restrict__ Wv0,
                          const float* __restrict__ Wj1, const float* __restrict__ Wi1,
                          const float* __restrict__ sw1, const float* __restrict__ sb1,
                          const float* __restrict__ Wq1, const float* __restrict__ Wk1,
                          const float* __restrict__ Wv1,
                          __nv_bfloat16* __restrict__ wj0t, __nv_bfloat16* __restrict__ w0pack,
                          float* __restrict__ b0pack,
                          __nv_bfloat16* __restrict__ wqkv0t,
                          __nv_bfloat16* __restrict__ w1pack, float* __restrict__ b1pack,
                          __nv_bfloat16* __restrict__ wqkv1t,
                          uint4* __restrict__ den0z, uint4* __restrict__ z0z,
                          uint4* __restrict__ den1z, uint4* __restrict__ z1z)
{
    int b = blockIdx.x;
    int t = threadIdx.x;
    const uint4 zero4 = make_uint4(0u, 0u, 0u, 0u);

    if (b < B_S0) {                         // wj0t / w0pack / b0pack
        int z = b >> 7;                     // 128 blocks each
        int i = ((b & 127) << 8) + t;       // < 32768
        int k = i >> 8, n = i & 255;
        const float* src = (z == 0) ? Wj0 : (z == 1) ? Wi0 : sw0;
        __nv_bfloat16 v = __float2bfloat16(src[i]);
        if (z == 0) {
            wj0t[(size_t)n * IN_DIM + k] = v;
            if (i < 256) b0pack[i] = 0.f;
        } else {
            int off = (z == 2) ? 256 : 0;
            w0pack[((size_t)(off + n)) * IN_DIM + k] = v;
            if (z == 2 && i < 256) b0pack[256 + i] = sb0[i];
        }
        return;
    }
    b -= B_S0;
    if (b < B_S1) {                         // wqkv0t (15 x 65536)
        int z = b >> 8;                     // 256 blocks each
        int i = ((b & 255) << 8) + t;       // < 65536
        int which = z / R_NUM, r = z % R_NUM;
        const float* src = ((which == 0) ? Wq0 : (which == 1) ? Wk0 : Wv0)
                           + (size_t)r * HC0 * HC0;
        int k = i >> 8, n = i & 255;
        wqkv0t[(size_t)z * HC0 * HC0 + (size_t)n * HC0 + k] = __float2bfloat16(src[i]);
        return;
    }
    b -= B_S1;
    if (b < B_S2) {                         // w1pack / b1pack (3 x 10240)
        int z = b / 40;
        int i = (b % 40) * 256 + t;         // < 10240
        int k = i / C1, col = i - k * C1;
        const float* src = (z == 0) ? Wj1 : (z == 1) ? Wi1 : sw1;
        w1pack[(size_t)(z * C1 + col) * HC0 + k] = __float2bfloat16(src[i]);
        if (z == 0 && i < 80) b1pack[i] = 0.f;
        if (z == 2 && i < C1) b1pack[80 + i] = sb1[i];
        return;
    }
    b -= B_S2;
    if (b < B_S3) {                         // wqkv1t (5 x 7680)
        int r = b / 30;
        int i = (b % 30) * 256 + t;         // < 7680
        int n = i >> 6, k = i & 63;
        int which = n / C1, col = n - which * C1;
        float v = 0.f;
        if (k < C1) {
            const float* src = ((which == 0) ? Wq1 : (which == 1) ? Wk1 : Wv1)
                               + (size_t)r * C1 * C1;
            v = src[k * C1 + col];
        }
        wqkv1t[(size_t)r * 120 * 64 + i] = __float2bfloat16(v);
        return;
    }
    b -= B_S3;
    if (b < B_S4) {                         // zero den0 (75000 uint4)
        int i = (b << 8) + t;
        if (i < 75000) den0z[i] = zero4;
        return;
    }
    b -= B_S4;
    if (b < B_S5) {                         // zero z0bf (2400000 uint4)
        int i = (b << 8) + t;
        z0z[i] = zero4;
        return;
    }
    b -= B_S5;
    if (b < B_S6) {                         // zero den1 (18750 uint4)
        int i = (b << 8) + t;
        if (i < 18750) den1z[i] = zero4;
        return;
    }
    b -= B_S6;
    {                                       // zero z1bf (375000 uint4)
        int i = (b << 8) + t;
        if (i < 375000) z1z[i] = zero4;
    }
}

// ---------------- fused edge kernels (unnormalized scatter) ----------------
__global__ void edge_fused0(const int* __restrict__ src, const int* __restrict__ tgt,
                            const int* __restrict__ et,
                            const float* __restrict__ hj,
                            const float* __restrict__ hall,
                            const float* __restrict__ attj, const float* __restrict__ atti,
                            float* __restrict__ den, __nv_bfloat162* __restrict__ z,
                            int E)
{
    int w = (blockIdx.x * blockDim.x + threadIdx.x) >> 5;
    int lane = threadIdx.x & 31;
    if (w >= E) return;
    int gn = tgt[w];
    if (gn >= N2T) return;
    int t = et[w], s = src[w];
    const float* hjr = hj + (size_t)s * 256;
    const float* hir = hall + (size_t)gn * 512;
    int h = lane >> 3, j = lane & 7;
    const float* ajh = attj + ((size_t)t * 4 + h) * 64;
    const float* aih = atti + ((size_t)t * 4 + h) * 64;
    float acc = 0.f;
#pragma unroll
    for (int u = 0; u < 8; u++) {
        int c = j + 8 * u;
        acc += ajh[c] * hjr[h * 64 + c] + aih[c] * hir[h * 64 + c];
    }
#pragma unroll
    for (int o = 4; o; o >>= 1) acc += __shfl_xor_sync(0xffffffffu, acc, o);
    float a = acc >= 0.f ? acc : 0.2f * acc;
    float ex = expf(a);
    if (j == 0) atomicAdd(&den[((size_t)gn * R_NUM + t) * 4 + h], ex);
    float exh[4];
#pragma unroll
    for (int hh = 0; hh < 4; hh++) exh[hh] = __shfl_sync(0xffffffffu, ex, hh * 8);
    __nv_bfloat162* zr = z + ((size_t)t * N2T + gn) * 128;
#pragma unroll
    for (int u = 0; u < 4; u++) {
        int c2 = lane + 32 * u;
        float e = exh[u];
        __nv_bfloat162 val = __floats2bfloat162_rn(e * hjr[2 * c2], e * hjr[2 * c2 + 1]);
        atomicAdd(&zr[c2], val);
    }
}

__global__ void edge_fused1(const int* __restrict__ src, const int* __restrict__ tgt,
                            const int* __restrict__ et,
                            const float* __restrict__ hall,
                            const float* __restrict__ attj, const float* __restrict__ atti,
                            float* __restrict__ den, __nv_bfloat162* __restrict__ z,
                            int E)
{
    int w = (blockIdx.x * blockDim.x + threadIdx.x) >> 5;
    int lane = threadIdx.x & 31;
    if (w >= E) return;
    int gn = tgt[w];
    int t = et[w], s = src[w];
    const float* hjr = hall + (size_t)s * 120;
    const float* hir = hall + (size_t)gn * 120 + 40;
    const float* aj = attj + (size_t)t * 40;
    const float* ai = atti + (size_t)t * 40;
    float acc = aj[lane] * hjr[lane] + ai[lane] * hir[lane];
    if (lane < 8) acc += aj[lane + 32] * hjr[lane + 32] + ai[lane + 32] * hir[lane + 32];
#pragma unroll
    for (int o = 16; o; o >>= 1) acc += __shfl_xor_sync(0xffffffffu, acc, o);
    float a = acc >= 0.f ? acc : 0.2f * acc;
    float ex = expf(a);
    if (lane == 0) atomicAdd(&den[(size_t)gn * R_NUM + t], ex);
    __nv_bfloat162* zr = z + ((size_t)t * N2T + gn) * 20;
    if (lane < 20) {
        __nv_bfloat162 val = __floats2bfloat162_rn(ex * hjr[2 * lane], ex * hjr[2 * lane + 1]);
        atomicAdd(&zr[lane], val);
    }
}

// ---------------- normalize / pad ----------------
__global__ void z0_norm(__nv_bfloat162* __restrict__ z, const float* __restrict__ den)
{
    size_t i = (size_t)blockIdx.x * 256 + threadIdx.x;
    const size_t tot = (size_t)R_NUM * N2T * 128;
    if (i >= tot) return;
    int c2 = i & 127;
    size_t row = i >> 7;
    int r = row / N2T; int n = (int)(row - (size_t)r * N2T);
    int h = c2 >> 5;
    float d = fmaxf(den[((size_t)n * R_NUM + r) * 4 + h], 1e-16f);
    float inv = __fdividef(1.f, d);
    __nv_bfloat162 v = z[i];
    z[i] = __floats2bfloat162_rn(__low2float(v) * inv, __high2float(v) * inv);
}

__global__ void z1_pad(const __nv_bfloat16* __restrict__ z, const float* __restrict__ den,
                       __nv_bfloat16* __restrict__ out)
{
    int i = blockIdx.x * 256 + threadIdx.x;
    const int tot = R_NUM * N2T * 64;
    if (i >= tot) return;
    int c = i & 63;
    int row = i >> 6;
    int r = row / N2T; int n = row - r * N2T;
    float v = 0.f;
    if (c < 40) {
        float inv = __fdividef(1.f, fmaxf(den[(size_t)n * R_NUM + r], 1e-16f));
        v = __bfloat162float(z[(size_t)row * 40 + c]) * inv;
    }
    out[i] = __float2bfloat16(v);
}

// ---------------- bilevel relation attention ----------------
__device__ __forceinline__ void relcoeff(const float psi[R_NUM][R_NUM],
                                         const float* wrel, float coeff[R_NUM])
{
#pragma unroll
    for (int s = 0; s < R_NUM; s++) coeff[s] = 0.f;
#pragma unroll
    for (int r = 0; r < R_NUM; r++) {
        float rsum = 0.f;
#pragma unroll
        for (int s = 0; s < R_NUM; s++) rsum += psi[r][s];
        float pv[R_NUM], mx = -INFINITY;
#pragma unroll
        for (int s = 0; s < R_NUM; s++) {
            float xx = psi[r][s];
            bool masked = (xx == 0.f) && (rsum != 0.f);
            pv[s] = masked ? -INFINITY : xx;
            mx = fmaxf(mx, pv[s]);
        }
        float pe[R_NUM], se = 0.f;
#pragma unroll
        for (int s = 0; s < R_NUM; s++) {
            float e = isinf(pv[s]) ? 0.f : expf(pv[s] - mx);
            pe[s] = e; se += e;
        }
        float inv = wrel[r] / se;
#pragma unroll
        for (int s = 0; s < R_NUM; s++) coeff[s] += pe[s] * inv;
    }
}

// layer0: warp per (n,h). q/k/v bf16 [R][N2T][256]; self from h0all; out bf16 + relu
__global__ void attn0_kernel(const __nv_bfloat16* __restrict__ q,
                             const __nv_bfloat16* __restrict__ k,
                             const __nv_bfloat16* __restrict__ v,
                             const float* __restrict__ wrel,
                             const float* __restrict__ hall,
                             __nv_bfloat16* __restrict__ outbf)
{
    int w = (blockIdx.x * blockDim.x + threadIdx.x) >> 5;
    int lane = threadIdx.x & 31;
    if (w >= N2T * 4) return;
    int n = w >> 2, h = w & 3;
    size_t base = (size_t)n * 256 + h * 64;
    const size_t rst = (size_t)N2T * 256;
    int c0 = lane, c1 = lane + 32;

    float qv[R_NUM][2], kv[R_NUM][2], vv[R_NUM][2];
#pragma unroll
    for (int r = 0; r < R_NUM; r++) {
        size_t o = (size_t)r * rst + base;
        qv[r][0] = __bfloat162float(q[o + c0]); qv[r][1] = __bfloat162float(q[o + c1]);
        kv[r][0] = __bfloat162float(k[o + c0]); kv[r][1] = __bfloat162float(k[o + c1]);
        vv[r][0] = __bfloat162float(v[o + c0]); vv[r][1] = __bfloat162float(v[o + c1]);
    }
    float psi[R_NUM][R_NUM];
#pragma unroll
    for (int r = 0; r < R_NUM; r++)
#pragma unroll
        for (int s = 0; s < R_NUM; s++) {
            float p = qv[r][0] * kv[s][0] + qv[r][1] * kv[s][1];
#pragma unroll
            for (int o = 16; o; o >>= 1) p += __shfl_xor_sync(0xffffffffu, p, o);
            psi[r][s] = p;
        }
    float coeff[R_NUM];
    relcoeff(psi, wrel, coeff);

    const float* self = hall + (size_t)n * 512 + 256 + h * 64;
#pragma unroll
    for (int jj = 0; jj < 2; jj++) {
        int c = lane + 32 * jj;
        float acc = 0.f;
#pragma unroll
        for (int s = 0; s < R_NUM; s++) acc += coeff[s] * vv[s][jj];
        float val = self[c] + acc;
        outbf[base + c] = __float2bfloat16(fmaxf(val, 0.f));
    }
}

// layer1: warp per node. qkv f32 [R][N2T][120]; fused log_softmax
__global__ void attn1_ls(const float* __restrict__ qkv, const float* __restrict__ wrel,
                         const float* __restrict__ hall, float* __restrict__ out)
{
    int w = (blockIdx.x * blockDim.x + threadIdx.x) >> 5;
    int lane = threadIdx.x & 31;
    if (w >= N2T) return;
    int n = w;
    const size_t rst = (size_t)N2T * 120;
    size_t base = (size_t)n * 120;
    bool ok1 = lane < 8;

    float qv[R_NUM][2], kv[R_NUM][2], vv[R_NUM][2];
#pragma unroll
    for (int r = 0; r < R_NUM; r++) {
        const float* p = qkv + (size_t)r * rst + base;
        qv[r][0] = p[lane];      qv[r][1] = ok1 ? p[32 + lane] : 0.f;
        kv[r][0] = p[40 + lane]; kv[r][1] = ok1 ? p[72 + lane] : 0.f;
        vv[r][0] = p[80 + lane]; vv[r][1] = ok1 ? p[112 + lane] : 0.f;
    }
    float psi[R_NUM][R_NUM];
#pragma unroll
    for (int r = 0; r < R_NUM; r++)
#pragma unroll
        for (int s = 0; s < R_NUM; s++) {
            float p = qv[r][0] * kv[s][0] + qv[r][1] * kv[s][1];
#pragma unroll
            for (int o = 16; o; o >>= 1) p += __shfl_xor_sync(0xffffffffu, p, o);
            psi[r][s] = p;
        }
    float coeff[R_NUM];
    relcoeff(psi, wrel, coeff);

    const float* self = hall + (size_t)n * 120 + 80;
    float a0 = 0.f, a1 = 0.f;
#pragma unroll
    for (int s = 0; s < R_NUM; s++) { a0 += coeff[s] * vv[s][0]; a1 += coeff[s] * vv[s][1]; }
    float v0 = self[lane] + a0;
    float v1 = ok1 ? self[32 + lane] + a1 : -INFINITY;

    float mx = fmaxf(v0, v1);
#pragma unroll
    for (int o = 16; o; o >>= 1) mx = fmaxf(mx, __shfl_xor_sync(0xffffffffu, mx, o));
    float se = expf(v0 - mx) + (ok1 ? expf(v1 - mx) : 0.f);
#pragma unroll
    for (int o = 16; o; o >>= 1) se += __shfl_xor_sync(0xffffffffu, se, o);
    float lse = mx + logf(se);
    out[(size_t)n * 40 + lane] = v0 - lse;
    if (ok1) out[(size_t)n * 40 + 32 + lane] = v1 - lse;
}

// ---------------- host ----------------
extern "C" void kernel_launch(void* const* d_in, const int* in_sizes, int n_in,
                              void* d_out, int out_size)
{
    const int*   n_id  = (const int*)d_in[0];
    const int*   lni   = (const int*)d_in[1];
    const int*   ei0   = (const int*)d_in[3];
    const int*   et0   = (const int*)d_in[4];
    const int*   ei1   = (const int*)d_in[5];
    const int*   et1   = (const int*)d_in[6];
    const float* emb   = (const float*)d_in[7];
    const float* Wj0   = (const float*)d_in[8];
    const float* Wi0   = (const float*)d_in[9];
    const float* attj0 = (const float*)d_in[10];
    const float* atti0 = (const float*)d_in[11];
    const float* Wq0   = (const float*)d_in[12];
    const float* Wk0   = (const float*)d_in[13];
    const float* Wv0   = (const float*)d_in[14];
    const float* sw0   = (const float*)d_in[15];
    const float* sb0   = (const float*)d_in[16];
    const float* Wrel0 = (const float*)d_in[17];
    const float* Wj1   = (const float*)d_in[18];
    const float* Wi1   = (const float*)d_in[19];
    const float* attj1 = (const float*)d_in[20];
    const float* atti1 = (const float*)d_in[21];
    const float* Wq1   = (const float*)d_in[22];
    const float* Wk1   = (const float*)d_in[23];
    const float* Wv1   = (const float*)d_in[24];
    const float* sw1   = (const float*)d_in[25];
    const float* sb1   = (const float*)d_in[26];
    const float* Wrel1 = (const float*)d_in[27];

    int E0 = in_sizes[4];
    int E1 = in_sizes[6];

    __nv_bfloat16 *xbf, *z0bf, *qkv0bf, *x1bf, *z1bf, *z1p;
    __nv_bfloat16 *wj0t, *w0pack, *wqkv0t, *w1pack, *wqkv1t;
    float *hj0, *h0all, *den0, *h1all, *den1, *qkv1, *b0pack, *b1pack;
    cudaGetSymbolAddress((void**)&xbf,    g_xbf);
    cudaGetSymbolAddress((void**)&hj0,    g_hj0);
    cudaGetSymbolAddress((void**)&h0all,  g_h0all);
    cudaGetSymbolAddress((void**)&den0,   g_den0);
    cudaGetSymbolAddress((void**)&z0bf,   g_z0bf);
    cudaGetSymbolAddress((void**)&qkv0bf, g_qkv0bf);
    cudaGetSymbolAddress((void**)&x1bf,   g_x1bf);
    cudaGetSymbolAddress((void**)&h1all,  g_h1all);
    cudaGetSymbolAddress((void**)&den1,   g_den1);
    cudaGetSymbolAddress((void**)&z1bf,   g_z1bf);
    cudaGetSymbolAddress((void**)&z1p,    g_z1p);
    cudaGetSymbolAddress((void**)&qkv1,   g_qkv1);
    cudaGetSymbolAddress((void**)&wj0t,   g_wj0t);
    cudaGetSymbolAddress((void**)&w0pack, g_w0pack);
    cudaGetSymbolAddress((void**)&b0pack, g_b0pack);
    cudaGetSymbolAddress((void**)&wqkv0t, g_wqkv0t);
    cudaGetSymbolAddress((void**)&w1pack, g_w1pack);
    cudaGetSymbolAddress((void**)&b1pack, g_b1pack);
    cudaGetSymbolAddress((void**)&wqkv1t, g_wqkv1t);

    // ---- prep (weights + zero-fills) + gather ----
    mega_prep<<<B_TOT, 256>>>(Wj0, Wi0, sw0, sb0, Wq0, Wk0, Wv0,
                              Wj1, Wi1, sw1, sb1, Wq1, Wk1, Wv1,
                              wj0t, w0pack, b0pack, wqkv0t, w1pack, b1pack, wqkv1t,
                              (uint4*)den0, (uint4*)z0bf, (uint4*)den1, (uint4*)z1bf);
    gather_bf<<<cdiv(N1T * 32, 256), 256>>>(emb, n_id, lni, xbf);

    // ---- layer 0 ----
    gemm_tc_f32<<<dim3(2, cdiv(N1T, TBM)), 256>>>(xbf, wj0t, nullptr, hj0, N1T, 256, IN_DIM);
    gemm_tc_f32<<<dim3(4, cdiv(N2T, TBM)), 256>>>(xbf, w0pack, b0pack, h0all, N2T, 512, IN_DIM);

    edge_fused0<<<cdiv(E0 * 32, 256), 256>>>(ei0, ei0 + E0, et0, hj0, h0all,
                                             attj0, atti0, den0,
                                             (__nv_bfloat162*)z0bf, E0);
    z0_norm<<<cdiv(R_NUM * N2T * 128, 256), 256>>>((__nv_bfloat162*)z0bf, den0);

    gemm_tc_qkv0<<<dim3(2, cdiv(N2T, TBM), 15), 256>>>(
        z0bf, (size_t)N2T * HC0,
        wqkv0t, (size_t)HC0 * HC0,
        qkv0bf, (size_t)N2T * HC0,
        N2T, HC0, HC0);

    {
        const __nv_bfloat16* q0 = qkv0bf;
        const __nv_bfloat16* k0 = qkv0bf + (size_t)R_NUM * N2T * HC0;
        const __nv_bfloat16* v0 = qkv0bf + (size_t)2 * R_NUM * N2T * HC0;
        attn0_kernel<<<cdiv(N2T * 4 * 32, 256), 256>>>(q0, k0, v0, Wrel0, h0all, x1bf);
    }

    // ---- layer 1 ----
    gemm_tc_f32<<<dim3(1, cdiv(N2T, TBM)), 256>>>(x1bf, w1pack, b1pack, h1all, N2T, 120, HC0);

    edge_fused1<<<cdiv(E1 * 32, 256), 256>>>(ei1, ei1 + E1, et1, h1all,
                                             attj1, atti1, den1,
                                             (__nv_bfloat162*)z1bf, E1);
    z1_pad<<<cdiv(R_NUM * N2T * 64, 256), 256>>>(z1bf, den1, z1p);

    gemm_tc_batch_f32<<<dim3(1, cdiv(N2T, TBM), R_NUM), 256>>>(
        z1p, (size_t)N2T * 64,
        wqkv1t, (size_t)120 * 64,
        qkv1, (size_t)N2T * 120,
        N2T, 120, 64);

    attn1_ls<<<cdiv(N2T * 32, 256), 256>>>(qkv1, Wrel1, h1all, (float*)d_out);
}